// round 6
// baseline (speedup 1.0000x reference)
#include <cuda_runtime.h>
#include <cuda_pipeline.h>
#include <cstdint>

// Problem constants
#define B_TOT 4096
#define SEQ   50
#define HID   256
#define G3    1536        // per-k row in WT: [ih_r|ih_z|ih_n|hh_r|hh_z|hh_n] = 2*768
#define TB    32          // batch rows per CTA
#define NCTA  (B_TOT / TB)  // 128
#define NT    512         // threads per CTA (16 warps, 4/SMSP)
#define KT    8           // k per tile
#define NTILE (HID / KT)  // 32

// smem layout (float offsets)
#define OFF_SWT 0                       // [2][KT][G3] = 24576
#define OFF_SHC 24576                   // [256][36]   = 9216  (C_s transposed, padded)
#define OFF_SHH 33792                   // [2][256][36] = 18432 (h double buffer, transposed)
#define OFF_SB  52224                   // [4][256] combined biases: r, z, in, hn
#define OFF_SG  53248                   // [32] gate G per step
#define SMEM_FLOATS 53280
#define SMEM_BYTES  (SMEM_FLOATS * 4)   // 213120 < 227KB

// W pre-transposed: WT[k*1536 + g], g<768 -> W_ih[g][k], else W_hh[g-768][k]
__device__ float g_WT[HID * G3];

__device__ __forceinline__ void fma2(unsigned long long& d,
                                     unsigned long long a,
                                     unsigned long long b) {
    asm("fma.rn.f32x2 %0, %1, %2, %0;" : "+l"(d) : "l"(a), "l"(b));
}
__device__ __forceinline__ unsigned long long splat2(float v) {
    unsigned long long r;
    asm("mov.b64 %0, {%1, %1};" : "=l"(r) : "f"(v));
    return r;
}
__device__ __forceinline__ void unpack2(unsigned long long v, float& lo, float& hi) {
    asm("mov.b64 {%0, %1}, %2;" : "=f"(lo), "=f"(hi) : "l"(v));
}

__device__ __forceinline__ float gru_cell(float xr, float xz, float xin, float xhn,
                                          float hprev, float g) {
    float r = __fdividef(1.f, 1.f + __expf(-xr));
    float z = __fdividef(1.f, 1.f + __expf(-xz));
    float t = xin + r * xhn;
    t = fminf(fmaxf(t, -30.f), 30.f);
    float e = __expf(-2.f * t);
    float n = __fdividef(1.f - e, 1.f + e);
    float hnew = (1.f - z) * n + z * hprev;
    return g * hnew + (1.f - g) * hprev;
}

__global__ void transpose_w_kernel(const float* __restrict__ Wih,
                                   const float* __restrict__ Whh) {
    int idx = blockIdx.x * 256 + threadIdx.x;   // 1536 blocks * 256 = 393216
    int g = idx % G3;
    int k = idx / G3;
    float v = (g < 768) ? Wih[g * HID + k] : Whh[(g - 768) * HID + k];
    g_WT[idx] = v;
}

__global__ void __launch_bounds__(NT, 1)
gru_kernel(const float* __restrict__ C, const float* __restrict__ G,
           const float* __restrict__ b_ih, const float* __restrict__ b_hh,
           float* __restrict__ out)
{
    extern __shared__ float sm[];
    const int tid = threadIdx.x;
    const int jt  = tid & 63;     // 64 j-threads, 4 j each -> 256 hidden
    const int bg  = tid >> 6;     // 8 b-groups, 4 b each   -> 32 batch rows
    const int j0  = jt * 4;
    const int b0  = bg * 4;
    const int bbase = blockIdx.x * TB;

    // combined biases into smem
    for (int i = tid; i < HID; i += NT) {
        sm[OFF_SB + i]         = b_ih[i]        + b_hh[i];
        sm[OFF_SB + 256 + i]   = b_ih[256 + i]  + b_hh[256 + i];
        sm[OFF_SB + 512 + i]   = b_ih[512 + i];
        sm[OFF_SB + 768 + i]   = b_hh[512 + i];
    }
    // h0 = 0 (buffer 0)
    for (int i = tid; i < 256 * 36; i += NT) sm[OFF_SHH + i] = 0.f;

    // ---- prefetch W tile 0 into buffer 0 (rolls across steps thereafter) ----
    #pragma unroll
    for (int i = 0; i < 6; ++i) {
        int f = i * 2048 + tid * 4;     // 12288 floats = KT*G3
        __pipeline_memcpy_async(&sm[OFF_SWT + f], &g_WT[f], 16);
    }
    __pipeline_commit();

    int ph = 0;

    #pragma unroll 1
    for (int s = 0; s < SEQ; ++s) {
        // ---- stage C[:, s, :] transposed into SHC (padded rows of 36) ----
        #pragma unroll
        for (int i = 0; i < 4; ++i) {
            int f = i * 2048 + tid * 4;     // 8192 floats
            int b = f >> 8;
            int h = f & 255;
            float4 v = *reinterpret_cast<const float4*>(
                C + ((size_t)(bbase + b) * SEQ + s) * HID + h);
            sm[OFF_SHC + (h + 0) * 36 + b] = v.x;
            sm[OFF_SHC + (h + 1) * 36 + b] = v.y;
            sm[OFF_SHC + (h + 2) * 36 + b] = v.z;
            sm[OFF_SHC + (h + 3) * 36 + b] = v.w;
        }
        if (tid < TB) sm[OFF_SG + tid] = G[(size_t)(bbase + tid) * SEQ + s];

        __pipeline_wait_prior(0);   // W tile 0 (prefetched last step / above)
        __syncthreads();

        // ---- init accumulators from biases (packed f32x2 pairs over j) ----
        unsigned long long ar[4][2], az[4][2], ain[4][2], ahn[4][2];
        {
            unsigned long long br0 = *(const unsigned long long*)&sm[OFF_SB + j0];
            unsigned long long br1 = *(const unsigned long long*)&sm[OFF_SB + j0 + 2];
            unsigned long long bz0 = *(const unsigned long long*)&sm[OFF_SB + 256 + j0];
            unsigned long long bz1 = *(const unsigned long long*)&sm[OFF_SB + 256 + j0 + 2];
            unsigned long long bi0 = *(const unsigned long long*)&sm[OFF_SB + 512 + j0];
            unsigned long long bi1 = *(const unsigned long long*)&sm[OFF_SB + 512 + j0 + 2];
            unsigned long long bh0 = *(const unsigned long long*)&sm[OFF_SB + 768 + j0];
            unsigned long long bh1 = *(const unsigned long long*)&sm[OFF_SB + 768 + j0 + 2];
            #pragma unroll
            for (int bb = 0; bb < 4; ++bb) {
                ar[bb][0] = br0;  ar[bb][1] = br1;
                az[bb][0] = bz0;  az[bb][1] = bz1;
                ain[bb][0] = bi0; ain[bb][1] = bi1;
                ahn[bb][0] = bh0; ahn[bb][1] = bh1;
            }
        }

        const float* shh = sm + OFF_SHH + ph * 9216;

        // ---- K loop: 32 tiles of 8, double-buffered W via cp.async ----
        int buf = 0;
        #pragma unroll 1
        for (int kt = 0; kt < NTILE; ++kt) {
            if (kt + 1 < NTILE) {
                const float* src = g_WT + (size_t)(kt + 1) * (KT * G3);
                float* dst = sm + OFF_SWT + (buf ^ 1) * (KT * G3);
                #pragma unroll
                for (int i = 0; i < 6; ++i) {
                    int f = i * 2048 + tid * 4;
                    __pipeline_memcpy_async(dst + f, src + f, 16);
                }
                __pipeline_commit();
            }
            const float* wt = sm + OFF_SWT + buf * (KT * G3);
            #pragma unroll
            for (int kk = 0; kk < KT; ++kk) {
                const int k = kt * KT + kk;
                const float* wrow = wt + kk * G3;
                ulonglong2 wir = *(const ulonglong2*)(wrow + j0);
                ulonglong2 wiz = *(const ulonglong2*)(wrow + 256 + j0);
                ulonglong2 win = *(const ulonglong2*)(wrow + 512 + j0);
                ulonglong2 whr = *(const ulonglong2*)(wrow + 768 + j0);
                ulonglong2 whz = *(const ulonglong2*)(wrow + 1024 + j0);
                ulonglong2 whn = *(const ulonglong2*)(wrow + 1280 + j0);
                float4 c0 = *(const float4*)(sm + OFF_SHC + k * 36 + b0);
                float4 h0 = *(const float4*)(shh + k * 36 + b0);
                float cs[4] = {c0.x, c0.y, c0.z, c0.w};
                float hs[4] = {h0.x, h0.y, h0.z, h0.w};
                #pragma unroll
                for (int bb = 0; bb < 4; ++bb) {
                    unsigned long long c2 = splat2(cs[bb]);
                    unsigned long long h2 = splat2(hs[bb]);
                    fma2(ar[bb][0],  c2, wir.x);  fma2(ar[bb][1],  c2, wir.y);
                    fma2(ar[bb][0],  h2, whr.x);  fma2(ar[bb][1],  h2, whr.y);
                    fma2(az[bb][0],  c2, wiz.x);  fma2(az[bb][1],  c2, wiz.y);
                    fma2(az[bb][0],  h2, whz.x);  fma2(az[bb][1],  h2, whz.y);
                    fma2(ain[bb][0], c2, win.x);  fma2(ain[bb][1], c2, win.y);
                    fma2(ahn[bb][0], h2, whn.x);  fma2(ahn[bb][1], h2, whn.y);
                }
            }
            if (kt + 1 < NTILE) __pipeline_wait_prior(0);
            __syncthreads();
            buf ^= 1;
        }

        // ---- prefetch W tile 0 for NEXT step into buffer 0 (now free),
        //      overlapping the epilogue ----
        if (s + 1 < SEQ) {
            #pragma unroll
            for (int i = 0; i < 6; ++i) {
                int f = i * 2048 + tid * 4;
                __pipeline_memcpy_async(&sm[OFF_SWT + f], &g_WT[f], 16);
            }
            __pipeline_commit();
        }

        // ---- epilogue: gates, h update, gated output; write to other h buffer ----
        float* shn = sm + OFF_SHH + (ph ^ 1) * 9216;
        #pragma unroll
        for (int p = 0; p < 2; ++p) {
            const int jA = j0 + 2 * p;
            const int jB = jA + 1;
            float4 hA0 = *(const float4*)(shh + jA * 36 + b0);
            float4 hB0 = *(const float4*)(shh + jB * 36 + b0);
            float holdA[4] = {hA0.x, hA0.y, hA0.z, hA0.w};
            float holdB[4] = {hB0.x, hB0.y, hB0.z, hB0.w};
            float resA[4], resB[4];
            #pragma unroll
            for (int bb = 0; bb < 4; ++bb) {
                float r0, r1, z0, z1, i0, i1, n0, n1;
                unpack2(ar[bb][p],  r0, r1);
                unpack2(az[bb][p],  z0, z1);
                unpack2(ain[bb][p], i0, i1);
                unpack2(ahn[bb][p], n0, n1);
                float g = sm[OFF_SG + b0 + bb];
                resA[bb] = gru_cell(r0, z0, i0, n0, holdA[bb], g);
                resB[bb] = gru_cell(r1, z1, i1, n1, holdB[bb], g);
            }
            *(float4*)(shn + jA * 36 + b0) = make_float4(resA[0], resA[1], resA[2], resA[3]);
            *(float4*)(shn + jB * 36 + b0) = make_float4(resB[0], resB[1], resB[2], resB[3]);
        }
        __syncthreads();
        ph ^= 1;
    }

    // ---- write final h: out[(bbase+b)*256 + j] ----
    const float* hf = sm + OFF_SHH + ph * 9216;
    {
        const int j    = tid & 255;
        const int half = tid >> 8;        // 0 or 1
        #pragma unroll
        for (int i = 0; i < 16; ++i) {
            int b = half * 16 + i;
            out[(size_t)(bbase + b) * HID + j] = hf[j * 36 + b];
        }
    }
}

extern "C" void kernel_launch(void* const* d_in, const int* in_sizes, int n_in,
                              void* d_out, int out_size) {
    const float* C   = (const float*)d_in[0];
    const float* G   = (const float*)d_in[1];
    const float* Wih = (const float*)d_in[2];
    const float* Whh = (const float*)d_in[3];
    const float* bih = (const float*)d_in[4];
    const float* bhh = (const float*)d_in[5];
    float* out = (float*)d_out;

    cudaFuncSetAttribute(gru_kernel, cudaFuncAttributeMaxDynamicSharedMemorySize,
                         SMEM_BYTES);

    transpose_w_kernel<<<1536, 256>>>(Wih, Whh);
    gru_kernel<<<NCTA, NT, SMEM_BYTES>>>(C, G, bih, bhh, out);
}

// round 9
// speedup vs baseline: 1.3426x; 1.3426x over previous
#include <cuda_runtime.h>
#include <cuda_pipeline.h>
#include <cuda_bf16.h>
#include <cstdint>

// ============================ Problem constants ============================
#define B_TOT 4096
#define SEQ   50
#define HID   256
#define NROW  (B_TOT * SEQ)      // 204800 rows of C (b*50+s)
#define NG    768                // 3 gates * 256
#define KC    768                // concatenated split-K (3 * 256)

// ============================ Device scratch ===============================
__device__ __nv_bfloat16 g_Ccat[(size_t)NROW * KC];   // [row][768] = [Chi|Chi|Clo]
__device__ __nv_bfloat16 g_Wcat[(size_t)NG * KC];     // [g][768]   = [Whi|Wlo|Whi]
__device__ float         g_gi[(size_t)NROW * NG];     // raw C @ W_ih^T
__device__ float         g_WT[HID * NG];              // scan: [k][g] of W_hh

// ============================ helpers ======================================
__device__ __forceinline__ uint32_t smem_u32(const void* p) {
    uint32_t a;
    asm("{ .reg .u64 t; cvta.to.shared.u64 t, %1; cvt.u32.u64 %0, t; }"
        : "=r"(a) : "l"(p));
    return a;
}

#define LDSM_X4(r0, r1, r2, r3, addr) \
    asm volatile("ldmatrix.sync.aligned.m8n8.x4.shared.b16 {%0,%1,%2,%3}, [%4];" \
        : "=r"(r0), "=r"(r1), "=r"(r2), "=r"(r3) : "r"(addr))

#define MMA16816(c, a, b0, b1) \
    asm volatile("mma.sync.aligned.m16n8k16.row.col.f32.bf16.bf16.f32 " \
        "{%0,%1,%2,%3}, {%4,%5,%6,%7}, {%8,%9}, {%0,%1,%2,%3};" \
        : "+f"((c)[0]), "+f"((c)[1]), "+f"((c)[2]), "+f"((c)[3]) \
        : "r"((a)[0]), "r"((a)[1]), "r"((a)[2]), "r"((a)[3]), "r"(b0), "r"(b1))

// f32x2 helpers
__device__ __forceinline__ void fma2(unsigned long long& d,
                                     unsigned long long a, unsigned long long b) {
    asm("fma.rn.f32x2 %0, %1, %2, %0;" : "+l"(d) : "l"(a), "l"(b));
}
__device__ __forceinline__ unsigned long long splat2(float v) {
    unsigned long long r;
    asm("mov.b64 %0, {%1, %1};" : "=l"(r) : "f"(v));
    return r;
}
__device__ __forceinline__ unsigned long long pack2(float a, float b) {
    unsigned long long r;
    asm("mov.b64 %0, {%1, %2};" : "=l"(r) : "f"(a), "f"(b));
    return r;
}
__device__ __forceinline__ void unpack2(unsigned long long v, float& lo, float& hi) {
    asm("mov.b64 {%0, %1}, %2;" : "=f"(lo), "=f"(hi) : "l"(v));
}

// ============================ Prep kernels =================================
__global__ void split_c_kernel(const float* __restrict__ C) {
    size_t idx = (size_t)blockIdx.x * 256 + threadIdx.x;   // over NROW*HID
    size_t r = idx >> 8;
    int k = (int)(idx & 255);
    float v = C[idx];
    __nv_bfloat16 hi = __float2bfloat16(v);
    __nv_bfloat16 lo = __float2bfloat16(v - __bfloat162float(hi));
    __nv_bfloat16* row = g_Ccat + r * KC;
    row[k] = hi; row[256 + k] = hi; row[512 + k] = lo;
}

__global__ void split_wih_kernel(const float* __restrict__ Wih) {
    int idx = blockIdx.x * 256 + threadIdx.x;              // over NG*HID
    int g = idx >> 8, k = idx & 255;
    float v = Wih[idx];
    __nv_bfloat16 hi = __float2bfloat16(v);
    __nv_bfloat16 lo = __float2bfloat16(v - __bfloat162float(hi));
    __nv_bfloat16* row = g_Wcat + (size_t)g * KC;
    row[k] = hi; row[256 + k] = lo; row[512 + k] = hi;
}

__global__ void transpose_whh_kernel(const float* __restrict__ Whh) {
    int idx = blockIdx.x * 256 + threadIdx.x;              // over NG*HID
    int g = idx / HID, k = idx % HID;
    g_WT[k * NG + g] = Whh[idx];
}

// ============================ Phase 1: gi GEMM (mma.sync) ==================
// gi[m, n] = sum_k Ccat[m,k] * Wcat[n,k]   (TN, K=768 folds bf16 3-split)
#define BM 128
#define BN 128
#define BK 64
#define NCHUNK (KC / BK)          // 12
#define PITCH  72                 // bf16 elems per smem row (144B = 9*16B)
#define ATILE  (BM * PITCH)       // elems per tile (A and B identical shape)
// smem layout: [A0][B0][A1][B1], each ATILE*2 bytes = 18432; total 73728
#define P1_SMEM (4 * ATILE * 2)

__device__ __forceinline__ void p1_load(__nv_bfloat16* adst, __nv_bfloat16* bdst,
                                        const __nv_bfloat16* asrc,
                                        const __nv_bfloat16* bsrc, int tid) {
    #pragma unroll
    for (int q = 0; q < 4; ++q) {                 // A: 128 rows x 64 k (8 segs)
        int i = q * 256 + tid;
        int row = i >> 3, seg = i & 7;
        __pipeline_memcpy_async(adst + row * PITCH + seg * 8,
                                asrc + (size_t)row * KC + seg * 8, 16);
    }
    #pragma unroll
    for (int q = 0; q < 4; ++q) {                 // B: 128 rows x 64 k
        int i = q * 256 + tid;
        int row = i >> 3, seg = i & 7;
        __pipeline_memcpy_async(bdst + row * PITCH + seg * 8,
                                bsrc + (size_t)row * KC + seg * 8, 16);
    }
    __pipeline_commit();
}

__global__ void __launch_bounds__(256)
phase1_mma_kernel() {
    extern __shared__ __nv_bfloat16 sh[];
    const int tid  = threadIdx.x;
    const int lane = tid & 31;
    const int wid  = tid >> 5;
    const int wm   = wid & 1;         // 2 warps over M -> 64 rows each
    const int wn   = wid >> 1;        // 4 warps over N -> 32 cols each
    const int n0   = blockIdx.x * BN;
    const size_t m0 = (size_t)blockIdx.y * BM;

    __nv_bfloat16* Abuf[2] = { sh,             sh + 2 * ATILE };
    __nv_bfloat16* Bbuf[2] = { sh + ATILE,     sh + 3 * ATILE };

    float c[4][4][4];
    #pragma unroll
    for (int i = 0; i < 4; ++i)
        #pragma unroll
        for (int j = 0; j < 4; ++j)
            #pragma unroll
            for (int q = 0; q < 4; ++q) c[i][j][q] = 0.f;

    const __nv_bfloat16* asrc0 = g_Ccat + m0 * KC;
    const __nv_bfloat16* bsrc0 = g_Wcat + (size_t)n0 * KC;

    p1_load(Abuf[0], Bbuf[0], asrc0, bsrc0, tid);

    // per-lane ldmatrix address components (element offsets)
    const int a_row = wm * 64 + (lane & 15);
    const int a_colp = (lane >> 4) * 8;
    const int b_row = wn * 32 + (lane & 7) + ((lane >> 4) << 3);
    const int b_colp = ((lane >> 3) & 1) << 3;

    #pragma unroll 1
    for (int ch = 0; ch < NCHUNK; ++ch) {
        if (ch + 1 < NCHUNK)
            p1_load(Abuf[(ch + 1) & 1], Bbuf[(ch + 1) & 1],
                    asrc0 + (ch + 1) * BK, bsrc0 + (ch + 1) * BK, tid);
        __pipeline_wait_prior((ch + 1 < NCHUNK) ? 1 : 0);
        __syncthreads();

        const uint32_t abase = smem_u32(Abuf[ch & 1]);
        const uint32_t bbase = smem_u32(Bbuf[ch & 1]);

        #pragma unroll
        for (int ks = 0; ks < 4; ++ks) {
            uint32_t a[4][4];
            #pragma unroll
            for (int mi = 0; mi < 4; ++mi) {
                uint32_t addr = abase +
                    ((a_row + mi * 16) * PITCH + ks * 16 + a_colp) * 2;
                LDSM_X4(a[mi][0], a[mi][1], a[mi][2], a[mi][3], addr);
            }
            #pragma unroll
            for (int np = 0; np < 2; ++np) {
                uint32_t b0, b1, b2, b3;
                uint32_t addr = bbase +
                    ((b_row + np * 16) * PITCH + ks * 16 + b_colp) * 2;
                LDSM_X4(b0, b1, b2, b3, addr);
                #pragma unroll
                for (int mi = 0; mi < 4; ++mi) {
                    MMA16816(c[mi][np * 2],     a[mi], b0, b1);
                    MMA16816(c[mi][np * 2 + 1], a[mi], b2, b3);
                }
            }
        }
        __syncthreads();
    }

    // epilogue: direct global stores (8B per store, quad-contiguous)
    const int r_base = (int)(wm * 64) + (lane >> 2);
    const int c_base = n0 + wn * 32 + (lane & 3) * 2;
    #pragma unroll
    for (int mi = 0; mi < 4; ++mi) {
        #pragma unroll
        for (int ni = 0; ni < 4; ++ni) {
            size_t row = m0 + r_base + mi * 16;
            int col = c_base + ni * 8;
            *(float2*)&g_gi[row * NG + col] =
                make_float2(c[mi][ni][0], c[mi][ni][1]);
            *(float2*)&g_gi[(row + 8) * NG + col] =
                make_float2(c[mi][ni][2], c[mi][ni][3]);
        }
    }
}

// ============================ Phase 2: scan ================================
#define TB    32
#define NCTA  (B_TOT / TB)        // 128
#define NT    256
#define KT    8
#define NTILE (HID / KT)          // 32

// smem (float offsets)
#define OFF_SWT 0                 // [2][KT][768] = 12288
#define OFF_SHH 12288             // [2][256][36] = 18432
#define OFF_SB  30720             // [4][256]
#define OFF_SG  31744             // [32]
#define SC_FLOATS 31776
#define SC_BYTES  (SC_FLOATS * 4) // 127104

__device__ __forceinline__ float gru_cell(float xr, float xz, float xin, float xhn,
                                          float hprev, float g) {
    float r = __fdividef(1.f, 1.f + __expf(-xr));
    float z = __fdividef(1.f, 1.f + __expf(-xz));
    float t = xin + r * xhn;
    t = fminf(fmaxf(t, -30.f), 30.f);
    float e = __expf(-2.f * t);
    float n = __fdividef(1.f - e, 1.f + e);
    float hnew = (1.f - z) * n + z * hprev;
    return g * hnew + (1.f - g) * hprev;
}

__global__ void __launch_bounds__(NT, 1)
gru_scan_kernel(const float* __restrict__ G,
                const float* __restrict__ b_ih, const float* __restrict__ b_hh,
                float* __restrict__ out)
{
    extern __shared__ float sm[];
    const int tid = threadIdx.x;
    const int jt  = tid & 63;
    const int bg  = tid >> 6;
    const int j0  = jt * 4;
    const int b0  = bg * 8;
    const int bbase = blockIdx.x * TB;

    for (int i = tid; i < HID; i += NT) {
        sm[OFF_SB + i]       = b_ih[i]       + b_hh[i];
        sm[OFF_SB + 256 + i] = b_ih[256 + i] + b_hh[256 + i];
        sm[OFF_SB + 512 + i] = b_ih[512 + i];
        sm[OFF_SB + 768 + i] = b_hh[512 + i];
    }
    for (int i = tid; i < 256 * 36; i += NT) sm[OFF_SHH + i] = 0.f;

    // prefetch W tile 0
    #pragma unroll
    for (int i = 0; i < 6; ++i) {
        int f = i * 1024 + tid * 4;     // 6144 floats = KT*768
        __pipeline_memcpy_async(&sm[OFF_SWT + f], &g_WT[f], 16);
    }
    __pipeline_commit();

    int ph = 0;

    #pragma unroll 1
    for (int s = 0; s < SEQ; ++s) {
        // gi loads for this step (issued early; consumed at init)
        float4 gr[8], gz[8], gn[8];
        #pragma unroll
        for (int bb = 0; bb < 8; ++bb) {
            const float* p = g_gi + ((size_t)(bbase + b0 + bb) * SEQ + s) * NG + j0;
            gr[bb] = *(const float4*)(p);
            gz[bb] = *(const float4*)(p + 256);
            gn[bb] = *(const float4*)(p + 512);
        }
        if (tid < TB) sm[OFF_SG + tid] = G[(size_t)(bbase + tid) * SEQ + s];

        __pipeline_wait_prior(0);
        __syncthreads();

        // init accumulators
        float4 sbr = *(const float4*)&sm[OFF_SB + j0];
        float4 sbz = *(const float4*)&sm[OFF_SB + 256 + j0];
        float4 sbi = *(const float4*)&sm[OFF_SB + 512 + j0];
        float4 sbh = *(const float4*)&sm[OFF_SB + 768 + j0];
        unsigned long long ar[8][2], az[8][2], ain[8][2], ahn[8][2];
        unsigned long long hb0 = pack2(sbh.x, sbh.y), hb1 = pack2(sbh.z, sbh.w);
        #pragma unroll
        for (int bb = 0; bb < 8; ++bb) {
            ar[bb][0]  = pack2(gr[bb].x + sbr.x, gr[bb].y + sbr.y);
            ar[bb][1]  = pack2(gr[bb].z + sbr.z, gr[bb].w + sbr.w);
            az[bb][0]  = pack2(gz[bb].x + sbz.x, gz[bb].y + sbz.y);
            az[bb][1]  = pack2(gz[bb].z + sbz.z, gz[bb].w + sbz.w);
            ain[bb][0] = pack2(gn[bb].x + sbi.x, gn[bb].y + sbi.y);
            ain[bb][1] = pack2(gn[bb].z + sbi.z, gn[bb].w + sbi.w);
            ahn[bb][0] = hb0;
            ahn[bb][1] = hb1;
        }

        const float* shh = sm + OFF_SHH + ph * 9216;

        int buf = 0;
        #pragma unroll 1
        for (int kt = 0; kt < NTILE; ++kt) {
            if (kt + 1 < NTILE) {
                const float* src = g_WT + (size_t)(kt + 1) * (KT * NG);
                float* dst = sm + OFF_SWT + (buf ^ 1) * (KT * NG);
                #pragma unroll
                for (int i = 0; i < 6; ++i) {
                    int f = i * 1024 + tid * 4;
                    __pipeline_memcpy_async(dst + f, src + f, 16);
                }
                __pipeline_commit();
            }
            const float* wt = sm + OFF_SWT + buf * (KT * NG);
            #pragma unroll
            for (int kk = 0; kk < KT; ++kk) {
                const int k = kt * KT + kk;
                const float* wrow = wt + kk * NG;
                ulonglong2 whr = *(const ulonglong2*)(wrow + j0);
                ulonglong2 whz = *(const ulonglong2*)(wrow + 256 + j0);
                ulonglong2 whn = *(const ulonglong2*)(wrow + 512 + j0);
                float4 h0 = *(const float4*)(shh + k * 36 + b0);
                float4 h1 = *(const float4*)(shh + k * 36 + b0 + 4);
                float hs[8] = {h0.x, h0.y, h0.z, h0.w, h1.x, h1.y, h1.z, h1.w};
                #pragma unroll
                for (int bb = 0; bb < 8; ++bb) {
                    unsigned long long h2 = splat2(hs[bb]);
                    fma2(ar[bb][0],  h2, whr.x);  fma2(ar[bb][1],  h2, whr.y);
                    fma2(az[bb][0],  h2, whz.x);  fma2(az[bb][1],  h2, whz.y);
                    fma2(ahn[bb][0], h2, whn.x);  fma2(ahn[bb][1], h2, whn.y);
                }
            }
            if (kt + 1 < NTILE) __pipeline_wait_prior(0);
            __syncthreads();
            buf ^= 1;
        }

        // prefetch W tile 0 for next step, overlapping epilogue
        if (s + 1 < SEQ) {
            #pragma unroll
            for (int i = 0; i < 6; ++i) {
                int f = i * 1024 + tid * 4;
                __pipeline_memcpy_async(&sm[OFF_SWT + f], &g_WT[f], 16);
            }
            __pipeline_commit();
        }

        float* shn = sm + OFF_SHH + (ph ^ 1) * 9216;
        #pragma unroll
        for (int p = 0; p < 2; ++p) {
            const int jA = j0 + 2 * p;
            const int jB = jA + 1;
            float4 hA0 = *(const float4*)(shh + jA * 36 + b0);
            float4 hA1 = *(const float4*)(shh + jA * 36 + b0 + 4);
            float4 hB0 = *(const float4*)(shh + jB * 36 + b0);
            float4 hB1 = *(const float4*)(shh + jB * 36 + b0 + 4);
            float holdA[8] = {hA0.x, hA0.y, hA0.z, hA0.w, hA1.x, hA1.y, hA1.z, hA1.w};
            float holdB[8] = {hB0.x, hB0.y, hB0.z, hB0.w, hB1.x, hB1.y, hB1.z, hB1.w};
            float resA[8], resB[8];
            #pragma unroll
            for (int bb = 0; bb < 8; ++bb) {
                float r0, r1, z0, z1, i0, i1, n0, n1;
                unpack2(ar[bb][p],  r0, r1);
                unpack2(az[bb][p],  z0, z1);
                unpack2(ain[bb][p], i0, i1);
                unpack2(ahn[bb][p], n0, n1);
                float g = sm[OFF_SG + b0 + bb];
                resA[bb] = gru_cell(r0, z0, i0, n0, holdA[bb], g);
                resB[bb] = gru_cell(r1, z1, i1, n1, holdB[bb], g);
            }
            *(float4*)(shn + jA * 36 + b0)     = make_float4(resA[0], resA[1], resA[2], resA[3]);
            *(float4*)(shn + jA * 36 + b0 + 4) = make_float4(resA[4], resA[5], resA[6], resA[7]);
            *(float4*)(shn + jB * 36 + b0)     = make_float4(resB[0], resB[1], resB[2], resB[3]);
            *(float4*)(shn + jB * 36 + b0 + 4) = make_float4(resB[4], resB[5], resB[6], resB[7]);
        }
        __syncthreads();
        ph ^= 1;
    }

    const float* hf = sm + OFF_SHH + ph * 9216;
    #pragma unroll
    for (int i = 0; i < TB; ++i) {
        out[(size_t)(bbase + i) * HID + tid] = hf[tid * 36 + i];
    }
}

// ============================ Launch =======================================
extern "C" void kernel_launch(void* const* d_in, const int* in_sizes, int n_in,
                              void* d_out, int out_size) {
    const float* C   = (const float*)d_in[0];
    const float* G   = (const float*)d_in[1];
    const float* Wih = (const float*)d_in[2];
    const float* Whh = (const float*)d_in[3];
    const float* bih = (const float*)d_in[4];
    const float* bhh = (const float*)d_in[5];
    float* out = (float*)d_out;

    cudaFuncSetAttribute(phase1_mma_kernel,
                         cudaFuncAttributeMaxDynamicSharedMemorySize, P1_SMEM);
    cudaFuncSetAttribute(gru_scan_kernel,
                         cudaFuncAttributeMaxDynamicSharedMemorySize, SC_BYTES);

    split_c_kernel<<<NROW, 256>>>(C);
    split_wih_kernel<<<NG, 256>>>(Wih);
    transpose_whh_kernel<<<NG, 256>>>(Whh);

    phase1_mma_kernel<<<dim3(NG / BN, NROW / BM), 256, P1_SMEM>>>();

    gru_scan_kernel<<<NCTA, NT, SC_BYTES>>>(G, bih, bhh, out);
}

// round 10
// speedup vs baseline: 1.3447x; 1.0016x over previous
#include <cuda_runtime.h>
#include <cuda_pipeline.h>
#include <cuda_bf16.h>
#include <cstdint>

// ============================ Problem constants ============================
#define B_TOT 4096
#define SEQ   50
#define HID   256
#define NROW  (B_TOT * SEQ)      // 204800 rows of C (b*50+s)
#define NG    768                // 3 gates * 256
#define KC    768                // concatenated split-K (3 * 256)

// ============================ Device scratch ===============================
__device__ __nv_bfloat16 g_Ccat[(size_t)NROW * KC];   // [row][768] = [Chi|Chi|Clo]
__device__ __nv_bfloat16 g_Wcat[(size_t)NG * KC];     // [g][768]   = [Whi|Wlo|Whi]
__device__ float         g_gi[(size_t)NROW * NG];     // gi + combined bias
__device__ __nv_bfloat16 g_Whi[NG * HID];             // W_hh hi  [768][256]
__device__ __nv_bfloat16 g_Wlo[NG * HID];             // W_hh lo  [768][256]
__device__ float         g_biasc[NG];                 // b_ih (+ b_hh for r,z)

// ============================ helpers ======================================
__device__ __forceinline__ uint32_t smem_u32(const void* p) {
    uint32_t a;
    asm("{ .reg .u64 t; cvta.to.shared.u64 t, %1; cvt.u32.u64 %0, t; }"
        : "=r"(a) : "l"(p));
    return a;
}

#define LDSM_X4(r0, r1, r2, r3, addr) \
    asm volatile("ldmatrix.sync.aligned.m8n8.x4.shared.b16 {%0,%1,%2,%3}, [%4];" \
        : "=r"(r0), "=r"(r1), "=r"(r2), "=r"(r3) : "r"(addr))

#define MMA16816(c, a, b0, b1) \
    asm volatile("mma.sync.aligned.m16n8k16.row.col.f32.bf16.bf16.f32 " \
        "{%0,%1,%2,%3}, {%4,%5,%6,%7}, {%8,%9}, {%0,%1,%2,%3};" \
        : "+f"((c)[0]), "+f"((c)[1]), "+f"((c)[2]), "+f"((c)[3]) \
        : "r"((a)[0]), "r"((a)[1]), "r"((a)[2]), "r"((a)[3]), "r"(b0), "r"(b1))

__device__ __forceinline__ float fast_sigmoid(float x) {
    return __fdividef(1.f, 1.f + __expf(-x));
}
__device__ __forceinline__ float fast_tanh(float x) {
    x = fminf(fmaxf(x, -30.f), 30.f);
    float e = __expf(-2.f * x);
    return __fdividef(1.f - e, 1.f + e);
}

// ============================ Prep kernels =================================
__global__ void split_c_kernel(const float* __restrict__ C) {
    size_t idx = (size_t)blockIdx.x * 256 + threadIdx.x;   // over NROW*HID
    size_t r = idx >> 8;
    int k = (int)(idx & 255);
    float v = C[idx];
    __nv_bfloat16 hi = __float2bfloat16(v);
    __nv_bfloat16 lo = __float2bfloat16(v - __bfloat162float(hi));
    __nv_bfloat16* row = g_Ccat + r * KC;
    row[k] = hi; row[256 + k] = hi; row[512 + k] = lo;
}

__global__ void split_wih_kernel(const float* __restrict__ Wih) {
    int idx = blockIdx.x * 256 + threadIdx.x;              // over NG*HID
    int g = idx >> 8, k = idx & 255;
    float v = Wih[idx];
    __nv_bfloat16 hi = __float2bfloat16(v);
    __nv_bfloat16 lo = __float2bfloat16(v - __bfloat162float(hi));
    __nv_bfloat16* row = g_Wcat + (size_t)g * KC;
    row[k] = hi; row[256 + k] = lo; row[512 + k] = hi;
}

__global__ void split_whh_kernel(const float* __restrict__ Whh) {
    int idx = blockIdx.x * 256 + threadIdx.x;              // over NG*HID
    float v = Whh[idx];
    __nv_bfloat16 hi = __float2bfloat16(v);
    g_Whi[idx] = hi;
    g_Wlo[idx] = __float2bfloat16(v - __bfloat162float(hi));
}

__global__ void biasc_kernel(const float* __restrict__ bih,
                             const float* __restrict__ bhh) {
    int n = blockIdx.x * 256 + threadIdx.x;                // 3 blocks
    g_biasc[n] = bih[n] + (n < 512 ? bhh[n] : 0.f);
}

// ============================ Phase 1: gi GEMM (mma.sync) ==================
#define BM 128
#define BN 128
#define BK 64
#define NCHUNK (KC / BK)          // 12
#define PITCH  72                 // bf16 elems per smem row (144B = 9*16B)
#define ATILE  (BM * PITCH)
#define P1_SMEM (4 * ATILE * 2)

__device__ __forceinline__ void p1_load(__nv_bfloat16* adst, __nv_bfloat16* bdst,
                                        const __nv_bfloat16* asrc,
                                        const __nv_bfloat16* bsrc, int tid) {
    #pragma unroll
    for (int q = 0; q < 4; ++q) {
        int i = q * 256 + tid;
        int row = i >> 3, seg = i & 7;
        __pipeline_memcpy_async(adst + row * PITCH + seg * 8,
                                asrc + (size_t)row * KC + seg * 8, 16);
    }
    #pragma unroll
    for (int q = 0; q < 4; ++q) {
        int i = q * 256 + tid;
        int row = i >> 3, seg = i & 7;
        __pipeline_memcpy_async(bdst + row * PITCH + seg * 8,
                                bsrc + (size_t)row * KC + seg * 8, 16);
    }
    __pipeline_commit();
}

__global__ void __launch_bounds__(256)
phase1_mma_kernel() {
    extern __shared__ __nv_bfloat16 sh[];
    const int tid  = threadIdx.x;
    const int lane = tid & 31;
    const int wid  = tid >> 5;
    const int wm   = wid & 1;
    const int wn   = wid >> 1;
    const int n0   = blockIdx.x * BN;
    const size_t m0 = (size_t)blockIdx.y * BM;

    __nv_bfloat16* Abuf[2] = { sh,         sh + 2 * ATILE };
    __nv_bfloat16* Bbuf[2] = { sh + ATILE, sh + 3 * ATILE };

    float c[4][4][4];
    #pragma unroll
    for (int i = 0; i < 4; ++i)
        #pragma unroll
        for (int j = 0; j < 4; ++j)
            #pragma unroll
            for (int q = 0; q < 4; ++q) c[i][j][q] = 0.f;

    const __nv_bfloat16* asrc0 = g_Ccat + m0 * KC;
    const __nv_bfloat16* bsrc0 = g_Wcat + (size_t)n0 * KC;

    p1_load(Abuf[0], Bbuf[0], asrc0, bsrc0, tid);

    const int a_row = wm * 64 + (lane & 15);
    const int a_colp = (lane >> 4) * 8;
    const int b_row = wn * 32 + (lane & 7) + ((lane >> 4) << 3);
    const int b_colp = ((lane >> 3) & 1) << 3;

    #pragma unroll 1
    for (int ch = 0; ch < NCHUNK; ++ch) {
        if (ch + 1 < NCHUNK)
            p1_load(Abuf[(ch + 1) & 1], Bbuf[(ch + 1) & 1],
                    asrc0 + (ch + 1) * BK, bsrc0 + (ch + 1) * BK, tid);
        __pipeline_wait_prior((ch + 1 < NCHUNK) ? 1 : 0);
        __syncthreads();

        const uint32_t abase = smem_u32(Abuf[ch & 1]);
        const uint32_t bbase = smem_u32(Bbuf[ch & 1]);

        #pragma unroll
        for (int ks = 0; ks < 4; ++ks) {
            uint32_t a[4][4];
            #pragma unroll
            for (int mi = 0; mi < 4; ++mi) {
                uint32_t addr = abase +
                    ((a_row + mi * 16) * PITCH + ks * 16 + a_colp) * 2;
                LDSM_X4(a[mi][0], a[mi][1], a[mi][2], a[mi][3], addr);
            }
            #pragma unroll
            for (int np = 0; np < 2; ++np) {
                uint32_t b0, b1, b2, b3;
                uint32_t addr = bbase +
                    ((b_row + np * 16) * PITCH + ks * 16 + b_colp) * 2;
                LDSM_X4(b0, b1, b2, b3, addr);
                #pragma unroll
                for (int mi = 0; mi < 4; ++mi) {
                    MMA16816(c[mi][np * 2],     a[mi], b0, b1);
                    MMA16816(c[mi][np * 2 + 1], a[mi], b2, b3);
                }
            }
        }
        __syncthreads();
    }

    // epilogue: add combined bias, store
    const int r_base = (int)(wm * 64) + (lane >> 2);
    const int c_base = n0 + wn * 32 + (lane & 3) * 2;
    #pragma unroll
    for (int ni = 0; ni < 4; ++ni) {
        int col = c_base + ni * 8;
        float2 bv = *(const float2*)&g_biasc[col];
        #pragma unroll
        for (int mi = 0; mi < 4; ++mi) {
            size_t row = m0 + r_base + mi * 16;
            *(float2*)&g_gi[row * NG + col] =
                make_float2(c[mi][ni][0] + bv.x, c[mi][ni][1] + bv.y);
            *(float2*)&g_gi[(row + 8) * NG + col] =
                make_float2(c[mi][ni][2] + bv.x, c[mi][ni][3] + bv.y);
        }
    }
}

// ============================ Phase 2: tensor-core scan ====================
// Per CTA: 32 batch rows, all 768 gates.  c = h_hi*W_hi + h_lo*W_hi + h_hi*W_lo
#define TB    32
#define NCTA  (B_TOT / TB)        // 128
#define SNT   256
#define KCH   16
#define NKCH  (HID / KCH)         // 16
#define SPB   24                  // B chunk pitch (elems), 48B = 3*16B
#define SPA   264                 // A pitch (elems), 528B = 33*16B
#define SPH   260                 // h pitch (floats)

#define OFF_BH  0                                   // [2][768*24] bf16 = 73728
#define OFF_BL  (OFF_BH + 2 * 768 * SPB * 2)        // 73728, same size
#define OFF_AHI (OFF_BL + 2 * 768 * SPB * 2)        // 147456, 32*264*2 = 16896
#define OFF_ALO (OFF_AHI + 32 * SPA * 2)            // 164352
#define OFF_H   (OFF_ALO + 32 * SPA * 2)            // 181248, 32*260*4 = 33280
#define OFF_BHN (OFF_H + 32 * SPH * 4)              // 214528, 1024
#define OFF_G   (OFF_BHN + 256 * 4)                 // 215552, 128
#define SCN_SMEM (OFF_G + 32 * 4)                   // 215680

__device__ __forceinline__ void scn_prefetch(char* smp, int st, int kc, int tid) {
    char* dh = smp + OFF_BH + st * (768 * SPB * 2);
    char* dl = smp + OFF_BL + st * (768 * SPB * 2);
    const __nv_bfloat16* srch = g_Whi + kc * KCH;
    const __nv_bfloat16* srcl = g_Wlo + kc * KCH;
    #pragma unroll
    for (int q = 0; q < 6; ++q) {           // 1536 (row,seg) over 768 rows x 2
        int i = q * 256 + tid;
        int row = i >> 1, seg = i & 1;
        __pipeline_memcpy_async(dh + (row * SPB + seg * 8) * 2,
                                srch + (size_t)row * HID + seg * 8, 16);
        __pipeline_memcpy_async(dl + (row * SPB + seg * 8) * 2,
                                srcl + (size_t)row * HID + seg * 8, 16);
    }
    __pipeline_commit();
}

__global__ void __launch_bounds__(SNT, 1)
gru_scan_tc(const float* __restrict__ G, const float* __restrict__ b_hh,
            float* __restrict__ out)
{
    extern __shared__ char smp[];
    const int tid  = threadIdx.x;
    const int lane = tid & 31;
    const int w    = tid >> 5;                 // 8 warps, each owns 3x32 n-cols
    const int bbase = blockIdx.x * TB;
    const int qrow = lane >> 2;
    const int qcol = (lane & 3) * 2;

    float* hS   = (float*)(smp + OFF_H);
    float* bhnS = (float*)(smp + OFF_BHN);
    float* gS   = (float*)(smp + OFF_G);

    for (int i = tid; i < 32 * SPH; i += SNT) hS[i] = 0.f;
    bhnS[tid] = b_hh[512 + tid];
    scn_prefetch(smp, 0, 0, tid);
    __syncthreads();

    // constant n-gate bias fragments (b_hh_n at this thread's j columns)
    float2 bnv[4];
    #pragma unroll
    for (int ni = 0; ni < 4; ++ni)
        bnv[ni] = *(const float2*)&bhnS[32 * w + 8 * ni + qcol];

    const uint32_t ahi_base = smem_u32(smp + OFF_AHI);
    const uint32_t alo_base = smem_u32(smp + OFF_ALO);
    const int arow = lane & 15;
    const int acp  = (lane >> 4) * 8;
    const int brl  = (lane & 7) + ((lane >> 4) << 3);
    const int bcp  = ((lane >> 3) & 1) * 8;

    #pragma unroll 1
    for (int s = 0; s < SEQ; ++s) {
        // ---- init accumulators from gi (r,z) / bias (n); keep i_n in regs --
        float c[2][12][4];
        float gin[2][4][4];
        #pragma unroll
        for (int mi = 0; mi < 2; ++mi) {
            size_t r0 = ((size_t)(bbase + 16 * mi + qrow) * SEQ + s) * NG;
            size_t r1 = r0 + (size_t)8 * SEQ * NG;
            #pragma unroll
            for (int ni = 0; ni < 12; ++ni) {
                int col = 256 * (ni >> 2) + 32 * w + 8 * (ni & 3) + qcol;
                float2 v0 = *(const float2*)&g_gi[r0 + col];
                float2 v1 = *(const float2*)&g_gi[r1 + col];
                if (ni < 8) {
                    c[mi][ni][0] = v0.x; c[mi][ni][1] = v0.y;
                    c[mi][ni][2] = v1.x; c[mi][ni][3] = v1.y;
                } else {
                    gin[mi][ni - 8][0] = v0.x; gin[mi][ni - 8][1] = v0.y;
                    gin[mi][ni - 8][2] = v1.x; gin[mi][ni - 8][3] = v1.y;
                    float2 bn = bnv[ni - 8];
                    c[mi][ni][0] = bn.x; c[mi][ni][1] = bn.y;
                    c[mi][ni][2] = bn.x; c[mi][ni][3] = bn.y;
                }
            }
        }
        if (tid < TB) gS[tid] = G[(size_t)(bbase + tid) * SEQ + s];

        // ---- convert h fp32 -> A_hi/A_lo bf16 ----
        {
            int b = tid >> 3, kb = (tid & 7) * 32;
            const float* hr = hS + b * SPH + kb;
            __nv_bfloat16* AH = (__nv_bfloat16*)(smp + OFF_AHI) + b * SPA + kb;
            __nv_bfloat16* AL = (__nv_bfloat16*)(smp + OFF_ALO) + b * SPA + kb;
            #pragma unroll
            for (int i = 0; i < 8; ++i) {
                float4 v = *(const float4*)(hr + 4 * i);
                __nv_bfloat16 h0 = __float2bfloat16(v.x);
                __nv_bfloat16 h1 = __float2bfloat16(v.y);
                __nv_bfloat16 h2 = __float2bfloat16(v.z);
                __nv_bfloat16 h3 = __float2bfloat16(v.w);
                __nv_bfloat16 l0 = __float2bfloat16(v.x - __bfloat162float(h0));
                __nv_bfloat16 l1 = __float2bfloat16(v.y - __bfloat162float(h1));
                __nv_bfloat16 l2 = __float2bfloat16(v.z - __bfloat162float(h2));
                __nv_bfloat16 l3 = __float2bfloat16(v.w - __bfloat162float(h3));
                *(__nv_bfloat162*)(AH + 4 * i)     = __halves2bfloat162(h0, h1);
                *(__nv_bfloat162*)(AH + 4 * i + 2) = __halves2bfloat162(h2, h3);
                *(__nv_bfloat162*)(AL + 4 * i)     = __halves2bfloat162(l0, l1);
                *(__nv_bfloat162*)(AL + 4 * i + 2) = __halves2bfloat162(l2, l3);
            }
        }

        // ---- K loop: 16 chunks of 16k, B double-buffered ----
        #pragma unroll 1
        for (int kc = 0; kc < NKCH; ++kc) {
            if (kc + 1 < NKCH) scn_prefetch(smp, (kc + 1) & 1, kc + 1, tid);
            __pipeline_wait_prior((kc + 1 < NKCH) ? 1 : 0);
            __syncthreads();

            const uint32_t bh_base = smem_u32(smp + OFF_BH + (kc & 1) * (768 * SPB * 2));
            const uint32_t bl_base = smem_u32(smp + OFF_BL + (kc & 1) * (768 * SPB * 2));

            uint32_t ah[2][4], al[2][4];
            #pragma unroll
            for (int mi = 0; mi < 2; ++mi) {
                uint32_t addr = ahi_base +
                    ((arow + 16 * mi) * SPA + kc * 16 + acp) * 2;
                LDSM_X4(ah[mi][0], ah[mi][1], ah[mi][2], ah[mi][3], addr);
                addr = alo_base + ((arow + 16 * mi) * SPA + kc * 16 + acp) * 2;
                LDSM_X4(al[mi][0], al[mi][1], al[mi][2], al[mi][3], addr);
            }
            #pragma unroll
            for (int np = 0; np < 6; ++np) {
                int nrow = 256 * (np >> 1) + 32 * w + 16 * (np & 1);
                uint32_t bh0, bh1, bh2, bh3, bl0, bl1, bl2, bl3;
                LDSM_X4(bh0, bh1, bh2, bh3,
                        bh_base + ((nrow + brl) * SPB + bcp) * 2);
                LDSM_X4(bl0, bl1, bl2, bl3,
                        bl_base + ((nrow + brl) * SPB + bcp) * 2);
                #pragma unroll
                for (int mi = 0; mi < 2; ++mi) {
                    MMA16816(c[mi][2 * np],     ah[mi], bh0, bh1);
                    MMA16816(c[mi][2 * np],     al[mi], bh0, bh1);
                    MMA16816(c[mi][2 * np],     ah[mi], bl0, bl1);
                    MMA16816(c[mi][2 * np + 1], ah[mi], bh2, bh3);
                    MMA16816(c[mi][2 * np + 1], al[mi], bh2, bh3);
                    MMA16816(c[mi][2 * np + 1], ah[mi], bl2, bl3);
                }
            }
            __syncthreads();
        }

        // prefetch next step's chunk0 during epilogue
        if (s + 1 < SEQ) scn_prefetch(smp, 0, 0, tid);

        // ---- epilogue: gates + gated h update (thread-local positions) ----
        #pragma unroll
        for (int mi = 0; mi < 2; ++mi) {
            #pragma unroll
            for (int ni = 0; ni < 4; ++ni) {
                int j = 32 * w + 8 * ni + qcol;
                #pragma unroll
                for (int rh = 0; rh < 2; ++rh) {
                    int b = 16 * mi + qrow + 8 * rh;
                    float g = gS[b];
                    float2 hp = *(const float2*)&hS[b * SPH + j];
                    float res[2];
                    #pragma unroll
                    for (int q2 = 0; q2 < 2; ++q2) {
                        int q = 2 * rh + q2;
                        float r = fast_sigmoid(c[mi][ni][q]);
                        float z = fast_sigmoid(c[mi][ni + 4][q]);
                        float hn = c[mi][ni + 8][q];         // h·Whn + b_hh_n
                        float n = fast_tanh(gin[mi][ni][q] + r * hn);
                        float hprev = q2 ? hp.y : hp.x;
                        float hnew = (1.f - z) * n + z * hprev;
                        res[q2] = g * hnew + (1.f - g) * hprev;
                    }
                    *(float2*)&hS[b * SPH + j] = make_float2(res[0], res[1]);
                }
            }
        }
        __syncthreads();
    }

    // ---- final output ----
    #pragma unroll 1
    for (int r = 0; r < TB; ++r)
        out[(size_t)(bbase + r) * HID + tid] = hS[r * SPH + tid];
}

// ============================ Launch =======================================
extern "C" void kernel_launch(void* const* d_in, const int* in_sizes, int n_in,
                              void* d_out, int out_size) {
    const float* C   = (const float*)d_in[0];
    const float* G   = (const float*)d_in[1];
    const float* Wih = (const float*)d_in[2];
    const float* Whh = (const float*)d_in[3];
    const float* bih = (const float*)d_in[4];
    const float* bhh = (const float*)d_in[5];
    float* out = (float*)d_out;

    cudaFuncSetAttribute(phase1_mma_kernel,
                         cudaFuncAttributeMaxDynamicSharedMemorySize, P1_SMEM);
    cudaFuncSetAttribute(gru_scan_tc,
                         cudaFuncAttributeMaxDynamicSharedMemorySize, SCN_SMEM);

    split_c_kernel<<<NROW, 256>>>(C);
    split_wih_kernel<<<NG, 256>>>(Wih);
    split_whh_kernel<<<NG, 256>>>(Whh);
    biasc_kernel<<<3, 256>>>(bih, bhh);

    phase1_mma_kernel<<<dim3(NG / BN, NROW / BM), 256, P1_SMEM>>>();

    gru_scan_tc<<<NCTA, SNT, SCN_SMEM>>>(G, bhh, out);
}

// round 11
// speedup vs baseline: 1.3525x; 1.0058x over previous
#include <cuda_runtime.h>
#include <cuda_pipeline.h>
#include <cuda_bf16.h>
#include <cstdint>

// ============================ Problem constants ============================
#define B_TOT 4096
#define SEQ   50
#define HID   256
#define NROW  (B_TOT * SEQ)      // 204800 rows of C (b*50+s)
#define NG    768                // 3 gates * 256
#define KC    768                // concatenated split-K (3 * 256)

// ============================ Device scratch ===============================
__device__ __nv_bfloat16 g_Ccat[(size_t)NROW * KC];   // [row][768] = [Chi|Chi|Clo]
__device__ __nv_bfloat16 g_Wcat[(size_t)NG * KC];     // [g][768]   = [Whi|Wlo|Whi]
__device__ float         g_gi[(size_t)NROW * NG];     // gi + combined bias
__device__ __nv_bfloat16 g_Whi[NG * HID];             // W_hh hi  [768][256]
__device__ __nv_bfloat16 g_Wlo[NG * HID];             // W_hh lo  [768][256]
__device__ float         g_biasc[NG];                 // b_ih (+ b_hh for r,z)

// ============================ helpers ======================================
__device__ __forceinline__ uint32_t smem_u32(const void* p) {
    uint32_t a;
    asm("{ .reg .u64 t; cvta.to.shared.u64 t, %1; cvt.u32.u64 %0, t; }"
        : "=r"(a) : "l"(p));
    return a;
}

#define LDSM_X4(r0, r1, r2, r3, addr) \
    asm volatile("ldmatrix.sync.aligned.m8n8.x4.shared.b16 {%0,%1,%2,%3}, [%4];" \
        : "=r"(r0), "=r"(r1), "=r"(r2), "=r"(r3) : "r"(addr))

#define MMA16816(c, a, b0, b1) \
    asm volatile("mma.sync.aligned.m16n8k16.row.col.f32.bf16.bf16.f32 " \
        "{%0,%1,%2,%3}, {%4,%5,%6,%7}, {%8,%9}, {%0,%1,%2,%3};" \
        : "+f"((c)[0]), "+f"((c)[1]), "+f"((c)[2]), "+f"((c)[3]) \
        : "r"((a)[0]), "r"((a)[1]), "r"((a)[2]), "r"((a)[3]), "r"(b0), "r"(b1))

__device__ __forceinline__ float fast_sigmoid(float x) {
    return __fdividef(1.f, 1.f + __expf(-x));
}
__device__ __forceinline__ float fast_tanh(float x) {
    x = fminf(fmaxf(x, -30.f), 30.f);
    float e = __expf(-2.f * x);
    return __fdividef(1.f - e, 1.f + e);
}

// ============================ Prep kernels =================================
__global__ void split_c_kernel(const float* __restrict__ C) {
    size_t idx = (size_t)blockIdx.x * 256 + threadIdx.x;   // over NROW*HID
    size_t r = idx >> 8;
    int k = (int)(idx & 255);
    float v = C[idx];
    __nv_bfloat16 hi = __float2bfloat16(v);
    __nv_bfloat16 lo = __float2bfloat16(v - __bfloat162float(hi));
    __nv_bfloat16* row = g_Ccat + r * KC;
    row[k] = hi; row[256 + k] = hi; row[512 + k] = lo;
}

__global__ void split_wih_kernel(const float* __restrict__ Wih) {
    int idx = blockIdx.x * 256 + threadIdx.x;              // over NG*HID
    int g = idx >> 8, k = idx & 255;
    float v = Wih[idx];
    __nv_bfloat16 hi = __float2bfloat16(v);
    __nv_bfloat16 lo = __float2bfloat16(v - __bfloat162float(hi));
    __nv_bfloat16* row = g_Wcat + (size_t)g * KC;
    row[k] = hi; row[256 + k] = lo; row[512 + k] = hi;
}

__global__ void split_whh_kernel(const float* __restrict__ Whh) {
    int idx = blockIdx.x * 256 + threadIdx.x;              // over NG*HID
    float v = Whh[idx];
    __nv_bfloat16 hi = __float2bfloat16(v);
    g_Whi[idx] = hi;
    g_Wlo[idx] = __float2bfloat16(v - __bfloat162float(hi));
}

__global__ void biasc_kernel(const float* __restrict__ bih,
                             const float* __restrict__ bhh) {
    int n = blockIdx.x * 256 + threadIdx.x;                // 3 blocks
    g_biasc[n] = bih[n] + (n < 512 ? bhh[n] : 0.f);
}

// ============================ Phase 1: gi GEMM (mma.sync) ==================
#define BM 128
#define BN 128
#define BK 64
#define NCHUNK (KC / BK)          // 12
#define PITCH  72                 // bf16 elems per smem row (144B = 9*16B)
#define ATILE  (BM * PITCH)
#define P1_SMEM (4 * ATILE * 2)

__device__ __forceinline__ void p1_load(__nv_bfloat16* adst, __nv_bfloat16* bdst,
                                        const __nv_bfloat16* asrc,
                                        const __nv_bfloat16* bsrc, int tid) {
    #pragma unroll
    for (int q = 0; q < 4; ++q) {
        int i = q * 256 + tid;
        int row = i >> 3, seg = i & 7;
        __pipeline_memcpy_async(adst + row * PITCH + seg * 8,
                                asrc + (size_t)row * KC + seg * 8, 16);
    }
    #pragma unroll
    for (int q = 0; q < 4; ++q) {
        int i = q * 256 + tid;
        int row = i >> 3, seg = i & 7;
        __pipeline_memcpy_async(bdst + row * PITCH + seg * 8,
                                bsrc + (size_t)row * KC + seg * 8, 16);
    }
    __pipeline_commit();
}

__global__ void __launch_bounds__(256)
phase1_mma_kernel() {
    extern __shared__ __nv_bfloat16 sh[];
    const int tid  = threadIdx.x;
    const int lane = tid & 31;
    const int wid  = tid >> 5;
    const int wm   = wid & 1;
    const int wn   = wid >> 1;
    const int n0   = blockIdx.x * BN;
    const size_t m0 = (size_t)blockIdx.y * BM;

    __nv_bfloat16* Abuf[2] = { sh,         sh + 2 * ATILE };
    __nv_bfloat16* Bbuf[2] = { sh + ATILE, sh + 3 * ATILE };

    float c[4][4][4];
    #pragma unroll
    for (int i = 0; i < 4; ++i)
        #pragma unroll
        for (int j = 0; j < 4; ++j)
            #pragma unroll
            for (int q = 0; q < 4; ++q) c[i][j][q] = 0.f;

    const __nv_bfloat16* asrc0 = g_Ccat + m0 * KC;
    const __nv_bfloat16* bsrc0 = g_Wcat + (size_t)n0 * KC;

    p1_load(Abuf[0], Bbuf[0], asrc0, bsrc0, tid);

    const int a_row = wm * 64 + (lane & 15);
    const int a_colp = (lane >> 4) * 8;
    const int b_row = wn * 32 + (lane & 7) + ((lane >> 4) << 3);
    const int b_colp = ((lane >> 3) & 1) << 3;

    #pragma unroll 1
    for (int ch = 0; ch < NCHUNK; ++ch) {
        if (ch + 1 < NCHUNK)
            p1_load(Abuf[(ch + 1) & 1], Bbuf[(ch + 1) & 1],
                    asrc0 + (ch + 1) * BK, bsrc0 + (ch + 1) * BK, tid);
        __pipeline_wait_prior((ch + 1 < NCHUNK) ? 1 : 0);
        __syncthreads();

        const uint32_t abase = smem_u32(Abuf[ch & 1]);
        const uint32_t bbase = smem_u32(Bbuf[ch & 1]);

        #pragma unroll
        for (int ks = 0; ks < 4; ++ks) {
            uint32_t a[4][4];
            #pragma unroll
            for (int mi = 0; mi < 4; ++mi) {
                uint32_t addr = abase +
                    ((a_row + mi * 16) * PITCH + ks * 16 + a_colp) * 2;
                LDSM_X4(a[mi][0], a[mi][1], a[mi][2], a[mi][3], addr);
            }
            #pragma unroll
            for (int np = 0; np < 2; ++np) {
                uint32_t b0, b1, b2, b3;
                uint32_t addr = bbase +
                    ((b_row + np * 16) * PITCH + ks * 16 + b_colp) * 2;
                LDSM_X4(b0, b1, b2, b3, addr);
                #pragma unroll
                for (int mi = 0; mi < 4; ++mi) {
                    MMA16816(c[mi][np * 2],     a[mi], b0, b1);
                    MMA16816(c[mi][np * 2 + 1], a[mi], b2, b3);
                }
            }
        }
        __syncthreads();
    }

    // epilogue: add combined bias, store
    const int r_base = (int)(wm * 64) + (lane >> 2);
    const int c_base = n0 + wn * 32 + (lane & 3) * 2;
    #pragma unroll
    for (int ni = 0; ni < 4; ++ni) {
        int col = c_base + ni * 8;
        float2 bv = *(const float2*)&g_biasc[col];
        #pragma unroll
        for (int mi = 0; mi < 4; ++mi) {
            size_t row = m0 + r_base + mi * 16;
            *(float2*)&g_gi[row * NG + col] =
                make_float2(c[mi][ni][0] + bv.x, c[mi][ni][1] + bv.y);
            *(float2*)&g_gi[(row + 8) * NG + col] =
                make_float2(c[mi][ni][2] + bv.x, c[mi][ni][3] + bv.y);
        }
    }
}

// ============================ Phase 2: tensor-core scan ====================
// Per CTA: 32 batch rows, all 768 gates.  c = h_hi*W_hi + h_lo*W_hi + h_hi*W_lo
// MMA issue is TERM-MAJOR across 8 independent accumulator tiles per gate to
// break the per-accumulator RAW chain (R10 bug: 3 chained HMMAs per tile).
#define TB    32
#define NCTA  (B_TOT / TB)        // 128
#define SNT   256
#define KCH   16
#define NKCH  (HID / KCH)         // 16
#define SPB   24                  // B chunk pitch (elems), 48B = 3*16B
#define SPA   264                 // A pitch (elems), 528B = 33*16B
#define SPH   260                 // h pitch (floats)

#define OFF_BH  0                                   // [2][768*24] bf16 = 73728
#define OFF_BL  (OFF_BH + 2 * 768 * SPB * 2)        // 73728, same size
#define OFF_AHI (OFF_BL + 2 * 768 * SPB * 2)        // 147456, 32*264*2 = 16896
#define OFF_ALO (OFF_AHI + 32 * SPA * 2)            // 164352
#define OFF_H   (OFF_ALO + 32 * SPA * 2)            // 181248, 32*260*4 = 33280
#define OFF_BHN (OFF_H + 32 * SPH * 4)              // 214528, 1024
#define OFF_G   (OFF_BHN + 256 * 4)                 // 215552, 128
#define SCN_SMEM (OFF_G + 32 * 4)                   // 215680

__device__ __forceinline__ void scn_prefetch(char* smp, int st, int kc, int tid) {
    char* dh = smp + OFF_BH + st * (768 * SPB * 2);
    char* dl = smp + OFF_BL + st * (768 * SPB * 2);
    const __nv_bfloat16* srch = g_Whi + kc * KCH;
    const __nv_bfloat16* srcl = g_Wlo + kc * KCH;
    #pragma unroll
    for (int q = 0; q < 6; ++q) {           // 1536 (row,seg) over 768 rows x 2
        int i = q * 256 + tid;
        int row = i >> 1, seg = i & 1;
        __pipeline_memcpy_async(dh + (row * SPB + seg * 8) * 2,
                                srch + (size_t)row * HID + seg * 8, 16);
        __pipeline_memcpy_async(dl + (row * SPB + seg * 8) * 2,
                                srcl + (size_t)row * HID + seg * 8, 16);
    }
    __pipeline_commit();
}

__global__ void __launch_bounds__(SNT, 1)
gru_scan_tc(const float* __restrict__ G, const float* __restrict__ b_hh,
            float* __restrict__ out)
{
    extern __shared__ char smp[];
    const int tid  = threadIdx.x;
    const int lane = tid & 31;
    const int w    = tid >> 5;                 // 8 warps, each owns 3x32 n-cols
    const int bbase = blockIdx.x * TB;
    const int qrow = lane >> 2;
    const int qcol = (lane & 3) * 2;

    float* hS   = (float*)(smp + OFF_H);
    float* bhnS = (float*)(smp + OFF_BHN);
    float* gS   = (float*)(smp + OFF_G);

    for (int i = tid; i < 32 * SPH; i += SNT) hS[i] = 0.f;
    bhnS[tid] = b_hh[512 + tid];
    scn_prefetch(smp, 0, 0, tid);
    __syncthreads();

    // constant n-gate bias fragments (b_hh_n at this thread's j columns)
    float2 bnv[4];
    #pragma unroll
    for (int ni = 0; ni < 4; ++ni)
        bnv[ni] = *(const float2*)&bhnS[32 * w + 8 * ni + qcol];

    const uint32_t ahi_base = smem_u32(smp + OFF_AHI);
    const uint32_t alo_base = smem_u32(smp + OFF_ALO);
    const int arow = lane & 15;
    const int acp  = (lane >> 4) * 8;
    const int brl  = (lane & 7) + ((lane >> 4) << 3);
    const int bcp  = ((lane >> 3) & 1) * 8;

    #pragma unroll 1
    for (int s = 0; s < SEQ; ++s) {
        // ---- init accumulators from gi (r,z) / bias (n); keep i_n in regs --
        float c[2][12][4];
        float gin[2][4][4];
        #pragma unroll
        for (int mi = 0; mi < 2; ++mi) {
            size_t r0 = ((size_t)(bbase + 16 * mi + qrow) * SEQ + s) * NG;
            size_t r1 = r0 + (size_t)8 * SEQ * NG;
            #pragma unroll
            for (int ni = 0; ni < 12; ++ni) {
                int col = 256 * (ni >> 2) + 32 * w + 8 * (ni & 3) + qcol;
                float2 v0 = *(const float2*)&g_gi[r0 + col];
                float2 v1 = *(const float2*)&g_gi[r1 + col];
                if (ni < 8) {
                    c[mi][ni][0] = v0.x; c[mi][ni][1] = v0.y;
                    c[mi][ni][2] = v1.x; c[mi][ni][3] = v1.y;
                } else {
                    gin[mi][ni - 8][0] = v0.x; gin[mi][ni - 8][1] = v0.y;
                    gin[mi][ni - 8][2] = v1.x; gin[mi][ni - 8][3] = v1.y;
                    float2 bn = bnv[ni - 8];
                    c[mi][ni][0] = bn.x; c[mi][ni][1] = bn.y;
                    c[mi][ni][2] = bn.x; c[mi][ni][3] = bn.y;
                }
            }
        }
        if (tid < TB) gS[tid] = G[(size_t)(bbase + tid) * SEQ + s];

        // ---- convert h fp32 -> A_hi/A_lo bf16 ----
        {
            int b = tid >> 3, kb = (tid & 7) * 32;
            const float* hr = hS + b * SPH + kb;
            __nv_bfloat16* AH = (__nv_bfloat16*)(smp + OFF_AHI) + b * SPA + kb;
            __nv_bfloat16* AL = (__nv_bfloat16*)(smp + OFF_ALO) + b * SPA + kb;
            #pragma unroll
            for (int i = 0; i < 8; ++i) {
                float4 v = *(const float4*)(hr + 4 * i);
                __nv_bfloat16 h0 = __float2bfloat16(v.x);
                __nv_bfloat16 h1 = __float2bfloat16(v.y);
                __nv_bfloat16 h2 = __float2bfloat16(v.z);
                __nv_bfloat16 h3 = __float2bfloat16(v.w);
                __nv_bfloat16 l0 = __float2bfloat16(v.x - __bfloat162float(h0));
                __nv_bfloat16 l1 = __float2bfloat16(v.y - __bfloat162float(h1));
                __nv_bfloat16 l2 = __float2bfloat16(v.z - __bfloat162float(h2));
                __nv_bfloat16 l3 = __float2bfloat16(v.w - __bfloat162float(h3));
                *(__nv_bfloat162*)(AH + 4 * i)     = __halves2bfloat162(h0, h1);
                *(__nv_bfloat162*)(AH + 4 * i + 2) = __halves2bfloat162(h2, h3);
                *(__nv_bfloat162*)(AL + 4 * i)     = __halves2bfloat162(l0, l1);
                *(__nv_bfloat162*)(AL + 4 * i + 2) = __halves2bfloat162(l2, l3);
            }
        }

        // ---- K loop: 16 chunks of 16k, B double-buffered ----
        #pragma unroll 1
        for (int kc = 0; kc < NKCH; ++kc) {
            if (kc + 1 < NKCH) scn_prefetch(smp, (kc + 1) & 1, kc + 1, tid);
            __pipeline_wait_prior((kc + 1 < NKCH) ? 1 : 0);
            __syncthreads();

            const uint32_t bh_base = smem_u32(smp + OFF_BH + (kc & 1) * (768 * SPB * 2));
            const uint32_t bl_base = smem_u32(smp + OFF_BL + (kc & 1) * (768 * SPB * 2));

            uint32_t ah[2][4], al[2][4];
            #pragma unroll
            for (int mi = 0; mi < 2; ++mi) {
                uint32_t addr = ahi_base +
                    ((arow + 16 * mi) * SPA + kc * 16 + acp) * 2;
                LDSM_X4(ah[mi][0], ah[mi][1], ah[mi][2], ah[mi][3], addr);
                addr = alo_base + ((arow + 16 * mi) * SPA + kc * 16 + acp) * 2;
                LDSM_X4(al[mi][0], al[mi][1], al[mi][2], al[mi][3], addr);
            }
            // per gate (np-pair): load 8 B frag regs (hi) + 8 (lo), then issue
            // 24 MMAs TERM-MAJOR over 8 independent tiles -> reuse distance 8.
            #pragma unroll
            for (int g3 = 0; g3 < 3; ++g3) {
                uint32_t bh[2][4], bl[2][4];
                #pragma unroll
                for (int t2 = 0; t2 < 2; ++t2) {
                    int nrow = 256 * g3 + 32 * w + 16 * t2;
                    LDSM_X4(bh[t2][0], bh[t2][1], bh[t2][2], bh[t2][3],
                            bh_base + ((nrow + brl) * SPB + bcp) * 2);
                    LDSM_X4(bl[t2][0], bl[t2][1], bl[t2][2], bl[t2][3],
                            bl_base + ((nrow + brl) * SPB + bcp) * 2);
                }
                // term 1: h_hi * W_hi   (8 independent accumulators)
                #pragma unroll
                for (int mi = 0; mi < 2; ++mi)
                    #pragma unroll
                    for (int t2 = 0; t2 < 2; ++t2) {
                        MMA16816(c[mi][4 * g3 + 2 * t2],     ah[mi], bh[t2][0], bh[t2][1]);
                        MMA16816(c[mi][4 * g3 + 2 * t2 + 1], ah[mi], bh[t2][2], bh[t2][3]);
                    }
                // term 2: h_lo * W_hi
                #pragma unroll
                for (int mi = 0; mi < 2; ++mi)
                    #pragma unroll
                    for (int t2 = 0; t2 < 2; ++t2) {
                        MMA16816(c[mi][4 * g3 + 2 * t2],     al[mi], bh[t2][0], bh[t2][1]);
                        MMA16816(c[mi][4 * g3 + 2 * t2 + 1], al[mi], bh[t2][2], bh[t2][3]);
                    }
                // term 3: h_hi * W_lo
                #pragma unroll
                for (int mi = 0; mi < 2; ++mi)
                    #pragma unroll
                    for (int t2 = 0; t2 < 2; ++t2) {
                        MMA16816(c[mi][4 * g3 + 2 * t2],     ah[mi], bl[t2][0], bl[t2][1]);
                        MMA16816(c[mi][4 * g3 + 2 * t2 + 1], ah[mi], bl[t2][2], bl[t2][3]);
                    }
            }
            __syncthreads();
        }

        // prefetch next step's chunk0 during epilogue
        if (s + 1 < SEQ) scn_prefetch(smp, 0, 0, tid);

        // ---- epilogue: gates + gated h update (thread-local positions) ----
        #pragma unroll
        for (int mi = 0; mi < 2; ++mi) {
            #pragma unroll
            for (int ni = 0; ni < 4; ++ni) {
                int j = 32 * w + 8 * ni + qcol;
                #pragma unroll
                for (int rh = 0; rh < 2; ++rh) {
                    int b = 16 * mi + qrow + 8 * rh;
                    float g = gS[b];
                    float2 hp = *(const float2*)&hS[b * SPH + j];
                    float res[2];
                    #pragma unroll
                    for (int q2 = 0; q2 < 2; ++q2) {
                        int q = 2 * rh + q2;
                        float r = fast_sigmoid(c[mi][ni][q]);
                        float z = fast_sigmoid(c[mi][ni + 4][q]);
                        float hn = c[mi][ni + 8][q];         // h·Whn + b_hh_n
                        float n = fast_tanh(gin[mi][ni][q] + r * hn);
                        float hprev = q2 ? hp.y : hp.x;
                        float hnew = (1.f - z) * n + z * hprev;
                        res[q2] = g * hnew + (1.f - g) * hprev;
                    }
                    *(float2*)&hS[b * SPH + j] = make_float2(res[0], res[1]);
                }
            }
        }
        __syncthreads();
    }

    // ---- final output ----
    #pragma unroll 1
    for (int r = 0; r < TB; ++r)
        out[(size_t)(bbase + r) * HID + tid] = hS[r * SPH + tid];
}

// ============================ Launch =======================================
extern "C" void kernel_launch(void* const* d_in, const int* in_sizes, int n_in,
                              void* d_out, int out_size) {
    const float* C   = (const float*)d_in[0];
    const float* G   = (const float*)d_in[1];
    const float* Wih = (const float*)d_in[2];
    const float* Whh = (const float*)d_in[3];
    const float* bih = (const float*)d_in[4];
    const float* bhh = (const float*)d_in[5];
    float* out = (float*)d_out;

    cudaFuncSetAttribute(phase1_mma_kernel,
                         cudaFuncAttributeMaxDynamicSharedMemorySize, P1_SMEM);
    cudaFuncSetAttribute(gru_scan_tc,
                         cudaFuncAttributeMaxDynamicSharedMemorySize, SCN_SMEM);

    split_c_kernel<<<NROW, 256>>>(C);
    split_wih_kernel<<<NG, 256>>>(Wih);
    split_whh_kernel<<<NG, 256>>>(Whh);
    biasc_kernel<<<3, 256>>>(bih, bhh);

    phase1_mma_kernel<<<dim3(NG / BN, NROW / BM), 256, P1_SMEM>>>();

    gru_scan_tc<<<NCTA, SNT, SCN_SMEM>>>(G, bhh, out);
}

// round 14
// speedup vs baseline: 2.1255x; 1.5715x over previous
#include <cuda_runtime.h>
#include <cuda_pipeline.h>
#include <cuda_bf16.h>
#include <cstdint>

// ============================ Problem constants ============================
#define B_TOT 4096
#define SEQ   50
#define HID   256
#define NROW  (B_TOT * SEQ)      // 204800 rows of C (b*50+s)
#define NG    768                // 3 gates * 256
#define KC    768                // concatenated split-K (3 * 256)

// ============================ Device scratch ===============================
__device__ __nv_bfloat16 g_Ccat[(size_t)NROW * KC];   // [row][768] = [Chi|Chi|Clo]
__device__ __nv_bfloat16 g_Wcat[(size_t)NG * KC];     // [g][768]   = [Whi|Wlo|Whi]
__device__ float         g_gi[(size_t)NROW * NG];     // gi + combined bias
__device__ float         g_biasc[NG];                 // b_ih (+ b_hh for r,z)
// W_hh in mma-B fragment order: tile (kc,nt) = 16x16, one uint4 per lane.
// tile index = kc*48 + nt;  element = [tile*32 + lane]
__device__ uint4         g_Wfh[16 * 48 * 32];         // hi split  (393 KB)
__device__ uint4         g_Wfl[16 * 48 * 32];         // lo split

// ============================ helpers ======================================
__device__ __forceinline__ uint32_t smem_u32(const void* p) {
    uint32_t a;
    asm("{ .reg .u64 t; cvta.to.shared.u64 t, %1; cvt.u32.u64 %0, t; }"
        : "=r"(a) : "l"(p));
    return a;
}

#define LDSM_X4(r0, r1, r2, r3, addr) \
    asm volatile("ldmatrix.sync.aligned.m8n8.x4.shared.b16 {%0,%1,%2,%3}, [%4];" \
        : "=r"(r0), "=r"(r1), "=r"(r2), "=r"(r3) : "r"(addr))

#define MMA16816(c, a, b0, b1) \
    asm volatile("mma.sync.aligned.m16n8k16.row.col.f32.bf16.bf16.f32 " \
        "{%0,%1,%2,%3}, {%4,%5,%6,%7}, {%8,%9}, {%0,%1,%2,%3};" \
        : "+f"((c)[0]), "+f"((c)[1]), "+f"((c)[2]), "+f"((c)[3]) \
        : "r"((a)[0]), "r"((a)[1]), "r"((a)[2]), "r"((a)[3]), "r"(b0), "r"(b1))

__device__ __forceinline__ float fast_sigmoid(float x) {
    return __fdividef(1.f, 1.f + __expf(-x));
}
__device__ __forceinline__ float fast_tanh(float x) {
    x = fminf(fmaxf(x, -30.f), 30.f);
    float e = __expf(-2.f * x);
    return __fdividef(1.f - e, 1.f + e);
}

__device__ __forceinline__ uint32_t pk_hi(float a, float b) {
    __nv_bfloat162 h = __floats2bfloat162_rn(a, b);
    return *(uint32_t*)&h;
}
__device__ __forceinline__ uint32_t pk_lo(float a, float b) {
    float ar = a - __bfloat162float(__float2bfloat16(a));
    float br = b - __bfloat162float(__float2bfloat16(b));
    __nv_bfloat162 h = __floats2bfloat162_rn(ar, br);
    return *(uint32_t*)&h;
}

// ============================ Prep kernels =================================
__global__ void split_c_kernel(const float* __restrict__ C) {
    size_t idx = (size_t)blockIdx.x * 256 + threadIdx.x;   // over NROW*HID
    size_t r = idx >> 8;
    int k = (int)(idx & 255);
    float v = C[idx];
    __nv_bfloat16 hi = __float2bfloat16(v);
    __nv_bfloat16 lo = __float2bfloat16(v - __bfloat162float(hi));
    __nv_bfloat16* row = g_Ccat + r * KC;
    row[k] = hi; row[256 + k] = hi; row[512 + k] = lo;
}

__global__ void split_wih_kernel(const float* __restrict__ Wih) {
    int idx = blockIdx.x * 256 + threadIdx.x;              // over NG*HID
    int g = idx >> 8, k = idx & 255;
    float v = Wih[idx];
    __nv_bfloat16 hi = __float2bfloat16(v);
    __nv_bfloat16 lo = __float2bfloat16(v - __bfloat162float(hi));
    __nv_bfloat16* row = g_Wcat + (size_t)g * KC;
    row[k] = hi; row[256 + k] = lo; row[512 + k] = hi;
}

// W_hh -> mma-B fragment order (hi/lo splits). 24576 lanes.
__global__ void wfrag_kernel(const float* __restrict__ Whh) {
    int t = blockIdx.x * 256 + threadIdx.x;    // 96 blocks
    int lane = t & 31;
    int tile = t >> 5;                          // kc*48 + nt
    int nt = tile % 48, kc = tile / 48;
    int r  = nt * 16 + (lane >> 2);
    int k0 = kc * 16 + (lane & 3) * 2;
    const float* w0 = Whh + (size_t)r * HID;
    const float* w8 = Whh + (size_t)(r + 8) * HID;
    float a0 = w0[k0], a1 = w0[k0 + 1], a8 = w0[k0 + 8], a9 = w0[k0 + 9];
    float b0 = w8[k0], b1 = w8[k0 + 1], b8 = w8[k0 + 8], b9 = w8[k0 + 9];
    uint4 vh, vl;
    vh.x = pk_hi(a0, a1); vh.y = pk_hi(a8, a9);
    vh.z = pk_hi(b0, b1); vh.w = pk_hi(b8, b9);
    vl.x = pk_lo(a0, a1); vl.y = pk_lo(a8, a9);
    vl.z = pk_lo(b0, b1); vl.w = pk_lo(b8, b9);
    g_Wfh[t] = vh;
    g_Wfl[t] = vl;
}

__global__ void biasc_kernel(const float* __restrict__ bih,
                             const float* __restrict__ bhh) {
    int n = blockIdx.x * 256 + threadIdx.x;                // 3 blocks
    g_biasc[n] = bih[n] + (n < 512 ? bhh[n] : 0.f);
}

// ============================ Phase 1: gi GEMM (mma.sync) ==================
#define BM 128
#define BN 128
#define BK 64
#define NCHUNK (KC / BK)          // 12
#define PITCH  72                 // bf16 elems per smem row (144B = 9*16B)
#define ATILE  (BM * PITCH)
#define P1_SMEM (4 * ATILE * 2)

__device__ __forceinline__ void p1_load(__nv_bfloat16* adst, __nv_bfloat16* bdst,
                                        const __nv_bfloat16* asrc,
                                        const __nv_bfloat16* bsrc, int tid) {
    #pragma unroll
    for (int q = 0; q < 4; ++q) {
        int i = q * 256 + tid;
        int row = i >> 3, seg = i & 7;
        __pipeline_memcpy_async(adst + row * PITCH + seg * 8,
                                asrc + (size_t)row * KC + seg * 8, 16);
    }
    #pragma unroll
    for (int q = 0; q < 4; ++q) {
        int i = q * 256 + tid;
        int row = i >> 3, seg = i & 7;
        __pipeline_memcpy_async(bdst + row * PITCH + seg * 8,
                                bsrc + (size_t)row * KC + seg * 8, 16);
    }
    __pipeline_commit();
}

__global__ void __launch_bounds__(256)
phase1_mma_kernel() {
    extern __shared__ __nv_bfloat16 sh[];
    const int tid  = threadIdx.x;
    const int lane = tid & 31;
    const int wid  = tid >> 5;
    const int wm   = wid & 1;
    const int wn   = wid >> 1;
    const int n0   = blockIdx.x * BN;
    const size_t m0 = (size_t)blockIdx.y * BM;

    __nv_bfloat16* Abuf[2] = { sh,         sh + 2 * ATILE };
    __nv_bfloat16* Bbuf[2] = { sh + ATILE, sh + 3 * ATILE };

    float c[4][4][4];
    #pragma unroll
    for (int i = 0; i < 4; ++i)
        #pragma unroll
        for (int j = 0; j < 4; ++j)
            #pragma unroll
            for (int q = 0; q < 4; ++q) c[i][j][q] = 0.f;

    const __nv_bfloat16* asrc0 = g_Ccat + m0 * KC;
    const __nv_bfloat16* bsrc0 = g_Wcat + (size_t)n0 * KC;

    p1_load(Abuf[0], Bbuf[0], asrc0, bsrc0, tid);

    const int a_row = wm * 64 + (lane & 15);
    const int a_colp = (lane >> 4) * 8;
    const int b_row = wn * 32 + (lane & 7) + ((lane >> 4) << 3);
    const int b_colp = ((lane >> 3) & 1) << 3;

    #pragma unroll 1
    for (int ch = 0; ch < NCHUNK; ++ch) {
        if (ch + 1 < NCHUNK)
            p1_load(Abuf[(ch + 1) & 1], Bbuf[(ch + 1) & 1],
                    asrc0 + (ch + 1) * BK, bsrc0 + (ch + 1) * BK, tid);
        __pipeline_wait_prior((ch + 1 < NCHUNK) ? 1 : 0);
        __syncthreads();

        const uint32_t abase = smem_u32(Abuf[ch & 1]);
        const uint32_t bbase = smem_u32(Bbuf[ch & 1]);

        #pragma unroll
        for (int ks = 0; ks < 4; ++ks) {
            uint32_t a[4][4];
            #pragma unroll
            for (int mi = 0; mi < 4; ++mi) {
                uint32_t addr = abase +
                    ((a_row + mi * 16) * PITCH + ks * 16 + a_colp) * 2;
                LDSM_X4(a[mi][0], a[mi][1], a[mi][2], a[mi][3], addr);
            }
            #pragma unroll
            for (int np = 0; np < 2; ++np) {
                uint32_t b0, b1, b2, b3;
                uint32_t addr = bbase +
                    ((b_row + np * 16) * PITCH + ks * 16 + b_colp) * 2;
                LDSM_X4(b0, b1, b2, b3, addr);
                #pragma unroll
                for (int mi = 0; mi < 4; ++mi) {
                    MMA16816(c[mi][np * 2],     a[mi], b0, b1);
                    MMA16816(c[mi][np * 2 + 1], a[mi], b2, b3);
                }
            }
        }
        __syncthreads();
    }

    // epilogue: add combined bias, store
    const int r_base = (int)(wm * 64) + (lane >> 2);
    const int c_base = n0 + wn * 32 + (lane & 3) * 2;
    #pragma unroll
    for (int ni = 0; ni < 4; ++ni) {
        int col = c_base + ni * 8;
        float2 bv = *(const float2*)&g_biasc[col];
        #pragma unroll
        for (int mi = 0; mi < 4; ++mi) {
            size_t row = m0 + r_base + mi * 16;
            *(float2*)&g_gi[row * NG + col] =
                make_float2(c[mi][ni][0] + bv.x, c[mi][ni][1] + bv.y);
            *(float2*)&g_gi[(row + 8) * NG + col] =
                make_float2(c[mi][ni][2] + bv.x, c[mi][ni][3] + bv.y);
        }
    }
}

// ============================ Phase 2: tensor-core scan ====================
// B fragments come straight from gmem (g_Wfh/g_Wfl, L2-resident) via LDG.128,
// double-buffered one 24-MMA stage ahead. No B smem, no W cp.async: the SMEM
// crossbar (R11's co-limiter with HMMA) now carries only A + h traffic.
#define TB    32
#define NCTA  (B_TOT / TB)        // 128
#define SNT   256
#define SPA   264                 // A pitch (elems), 528B = 33*16B
#define SPH   260                 // h pitch (floats)

#define OFF_AHI 0                                   // 32*264*2 = 16896
#define OFF_ALO (OFF_AHI + 32 * SPA * 2)            // 16896
#define OFF_H   (OFF_ALO + 32 * SPA * 2)            // 33792, 32*260*4 = 33280
#define OFF_BHN (OFF_H + 32 * SPH * 4)              // 67072, 1024
#define OFF_G   (OFF_BHN + 256 * 4)                 // 68096, 128
#define SCN_SMEM (OFF_G + 32 * 4)                   // 68224

__global__ void __launch_bounds__(SNT, 1)
gru_scan_tc(const float* __restrict__ G, const float* __restrict__ b_hh,
            float* __restrict__ out)
{
    extern __shared__ char smp[];
    const int tid  = threadIdx.x;
    const int lane = tid & 31;
    const int w    = tid >> 5;                 // 8 warps, each owns 3x32 n-cols
    const int bbase = blockIdx.x * TB;
    const int qrow = lane >> 2;
    const int qcol = (lane & 3) * 2;

    float* hS   = (float*)(smp + OFF_H);
    float* bhnS = (float*)(smp + OFF_BHN);
    float* gS   = (float*)(smp + OFF_G);

    for (int i = tid; i < 32 * SPH; i += SNT) hS[i] = 0.f;
    bhnS[tid] = b_hh[512 + tid];
    __syncthreads();

    // constant n-gate bias fragments
    float2 bnv[4];
    #pragma unroll
    for (int ni = 0; ni < 4; ++ni)
        bnv[ni] = *(const float2*)&bhnS[32 * w + 8 * ni + qcol];

    const uint32_t ahi_base = smem_u32(smp + OFF_AHI);
    const uint32_t alo_base = smem_u32(smp + OFF_ALO);
    const int arow = lane & 15;
    const int acp  = (lane >> 4) * 8;
    const int wf_lane = 2 * w * 32 + lane;     // lane offset within (kc,g3) row

    #pragma unroll 1
    for (int s = 0; s < SEQ; ++s) {
        // ---- gi loads (issued early) + gate G ----
        float2 gr[2][4], gz[2][4], gnv[2][4];
        #pragma unroll
        for (int mi = 0; mi < 2; ++mi) {
            size_t r0 = ((size_t)(bbase + 16 * mi + qrow) * SEQ + s) * NG;
            size_t r1 = r0 + (size_t)8 * SEQ * NG;
            #pragma unroll
            for (int ni = 0; ni < 4; ++ni) {
                int col = 32 * w + 8 * ni + qcol;
                gr[mi][ni]  = make_float2(g_gi[r0 + col],       g_gi[r1 + col]);
                gz[mi][ni]  = make_float2(g_gi[r0 + 256 + col], g_gi[r1 + 256 + col]);
                gnv[mi][ni] = make_float2(g_gi[r0 + 512 + col], g_gi[r1 + 512 + col]);
            }
        }
        if (tid < TB) gS[tid] = G[(size_t)(bbase + tid) * SEQ + s];

        // ---- convert h fp32 -> A_hi/A_lo bf16 ----
        {
            int b = tid >> 3, kb = (tid & 7) * 32;
            const float* hr = hS + b * SPH + kb;
            __nv_bfloat16* AH = (__nv_bfloat16*)(smp + OFF_AHI) + b * SPA + kb;
            __nv_bfloat16* AL = (__nv_bfloat16*)(smp + OFF_ALO) + b * SPA + kb;
            #pragma unroll
            for (int i = 0; i < 8; ++i) {
                float4 v = *(const float4*)(hr + 4 * i);
                __nv_bfloat16 h0 = __float2bfloat16(v.x);
                __nv_bfloat16 h1 = __float2bfloat16(v.y);
                __nv_bfloat16 h2 = __float2bfloat16(v.z);
                __nv_bfloat16 h3 = __float2bfloat16(v.w);
                __nv_bfloat16 l0 = __float2bfloat16(v.x - __bfloat162float(h0));
                __nv_bfloat16 l1 = __float2bfloat16(v.y - __bfloat162float(h1));
                __nv_bfloat16 l2 = __float2bfloat16(v.z - __bfloat162float(h2));
                __nv_bfloat16 l3 = __float2bfloat16(v.w - __bfloat162float(h3));
                *(__nv_bfloat162*)(AH + 4 * i)     = __halves2bfloat162(h0, h1);
                *(__nv_bfloat162*)(AH + 4 * i + 2) = __halves2bfloat162(h2, h3);
                *(__nv_bfloat162*)(AL + 4 * i)     = __halves2bfloat162(l0, l1);
                *(__nv_bfloat162*)(AL + 4 * i + 2) = __halves2bfloat162(l2, l3);
            }
        }
        __syncthreads();

        // ---- init accumulators ----
        float c[2][12][4];
        float gin[2][4][4];
        #pragma unroll
        for (int mi = 0; mi < 2; ++mi)
            #pragma unroll
            for (int ni = 0; ni < 4; ++ni) {
                c[mi][ni][0] = gr[mi][ni].x;     c[mi][ni][1] = 0.f;
                c[mi][ni][2] = gr[mi][ni].y;     c[mi][ni][3] = 0.f;
                c[mi][ni + 4][0] = gz[mi][ni].x; c[mi][ni + 4][1] = 0.f;
                c[mi][ni + 4][2] = gz[mi][ni].y; c[mi][ni + 4][3] = 0.f;
                gin[mi][ni][0] = gnv[mi][ni].x;  gin[mi][ni][2] = gnv[mi][ni].y;
                c[mi][ni + 8][0] = bnv[ni].x;    c[mi][ni + 8][1] = bnv[ni].y;
                c[mi][ni + 8][2] = bnv[ni].x;    c[mi][ni + 8][3] = bnv[ni].y;
            }
        // NOTE: gi loads above fetched only lane's qcol element pair start;
        // fetch the +1 element via the same float2 (done: .x/.y are the two
        // m-rows; the two j-columns come from loading float2 at col) —
        // reload properly below for the odd column.
        #pragma unroll
        for (int mi = 0; mi < 2; ++mi) {
            size_t r0 = ((size_t)(bbase + 16 * mi + qrow) * SEQ + s) * NG;
            size_t r1 = r0 + (size_t)8 * SEQ * NG;
            #pragma unroll
            for (int ni = 0; ni < 4; ++ni) {
                int col = 32 * w + 8 * ni + qcol;
                c[mi][ni][1] = g_gi[r0 + col + 1];
                c[mi][ni][3] = g_gi[r1 + col + 1];
                c[mi][ni + 4][1] = g_gi[r0 + 256 + col + 1];
                c[mi][ni + 4][3] = g_gi[r1 + 256 + col + 1];
                gin[mi][ni][1] = g_gi[r0 + 512 + col + 1];
                gin[mi][ni][3] = g_gi[r1 + 512 + col + 1];
            }
        }

        // ---- K loop: 48 stages (16 kc x 3 gates), B double-buffered LDG ----
        uint4 bh[2][2], bl[2][2];
        #pragma unroll
        for (int t2 = 0; t2 < 2; ++t2) {
            bh[0][t2] = g_Wfh[wf_lane + t2 * 32];
            bl[0][t2] = g_Wfl[wf_lane + t2 * 32];
        }
        #pragma unroll
        for (int kc = 0; kc < 16; ++kc) {
            uint32_t ah[2][4], al4[2][4];
            #pragma unroll
            for (int mi = 0; mi < 2; ++mi) {
                uint32_t addr = ahi_base +
                    ((arow + 16 * mi) * SPA + kc * 16 + acp) * 2;
                LDSM_X4(ah[mi][0], ah[mi][1], ah[mi][2], ah[mi][3], addr);
                addr = alo_base + ((arow + 16 * mi) * SPA + kc * 16 + acp) * 2;
                LDSM_X4(al4[mi][0], al4[mi][1], al4[mi][2], al4[mi][3], addr);
            }
            #pragma unroll
            for (int g3 = 0; g3 < 3; ++g3) {
                const int st = kc * 3 + g3;
                const int p  = st & 1, pn = p ^ 1;
                if (st + 1 < 48) {
                    const int stn = st + 1;
                    const int base = ((stn / 3) * 48 + (stn % 3) * 16) * 32;
                    #pragma unroll
                    for (int t2 = 0; t2 < 2; ++t2) {
                        bh[pn][t2] = g_Wfh[base + wf_lane + t2 * 32];
                        bl[pn][t2] = g_Wfl[base + wf_lane + t2 * 32];
                    }
                }
                // term 1: h_hi * W_hi  (8 independent accumulators)
                #pragma unroll
                for (int mi = 0; mi < 2; ++mi)
                    #pragma unroll
                    for (int t2 = 0; t2 < 2; ++t2) {
                        MMA16816(c[mi][4 * g3 + 2 * t2],     ah[mi], bh[p][t2].x, bh[p][t2].y);
                        MMA16816(c[mi][4 * g3 + 2 * t2 + 1], ah[mi], bh[p][t2].z, bh[p][t2].w);
                    }
                // term 2: h_lo * W_hi
                #pragma unroll
                for (int mi = 0; mi < 2; ++mi)
                    #pragma unroll
                    for (int t2 = 0; t2 < 2; ++t2) {
                        MMA16816(c[mi][4 * g3 + 2 * t2],     al4[mi], bh[p][t2].x, bh[p][t2].y);
                        MMA16816(c[mi][4 * g3 + 2 * t2 + 1], al4[mi], bh[p][t2].z, bh[p][t2].w);
                    }
                // term 3: h_hi * W_lo
                #pragma unroll
                for (int mi = 0; mi < 2; ++mi)
                    #pragma unroll
                    for (int t2 = 0; t2 < 2; ++t2) {
                        MMA16816(c[mi][4 * g3 + 2 * t2],     ah[mi], bl[p][t2].x, bl[p][t2].y);
                        MMA16816(c[mi][4 * g3 + 2 * t2 + 1], ah[mi], bl[p][t2].z, bl[p][t2].w);
                    }
            }
        }

        // ---- epilogue: gates + gated h update (thread-local positions) ----
        #pragma unroll
        for (int mi = 0; mi < 2; ++mi) {
            #pragma unroll
            for (int ni = 0; ni < 4; ++ni) {
                int j = 32 * w + 8 * ni + qcol;
                #pragma unroll
                for (int rh = 0; rh < 2; ++rh) {
                    int b = 16 * mi + qrow + 8 * rh;
                    float g = gS[b];
                    float2 hp = *(const float2*)&hS[b * SPH + j];
                    float res[2];
                    #pragma unroll
                    for (int q2 = 0; q2 < 2; ++q2) {
                        int q = 2 * rh + q2;
                        float r = fast_sigmoid(c[mi][ni][q]);
                        float z = fast_sigmoid(c[mi][ni + 4][q]);
                        float hn = c[mi][ni + 8][q];         // h·Whn + b_hh_n
                        float n = fast_tanh(gin[mi][ni][q] + r * hn);
                        float hprev = q2 ? hp.y : hp.x;
                        float hnew = (1.f - z) * n + z * hprev;
                        res[q2] = g * hnew + (1.f - g) * hprev;
                    }
                    *(float2*)&hS[b * SPH + j] = make_float2(res[0], res[1]);
                }
            }
        }
        __syncthreads();
    }

    // ---- final output ----
    #pragma unroll 1
    for (int r = 0; r < TB; ++r)
        out[(size_t)(bbase + r) * HID + tid] = hS[r * SPH + tid];
}

// ============================ Launch =======================================
extern "C" void kernel_launch(void* const* d_in, const int* in_sizes, int n_in,
                              void* d_out, int out_size) {
    const float* C   = (const float*)d_in[0];
    const float* G   = (const float*)d_in[1];
    const float* Wih = (const float*)d_in[2];
    const float* Whh = (const float*)d_in[3];
    const float* bih = (const float*)d_in[4];
    const float* bhh = (const float*)d_in[5];
    float* out = (float*)d_out;

    cudaFuncSetAttribute(phase1_mma_kernel,
                         cudaFuncAttributeMaxDynamicSharedMemorySize, P1_SMEM);
    cudaFuncSetAttribute(gru_scan_tc,
                         cudaFuncAttributeMaxDynamicSharedMemorySize, SCN_SMEM);

    split_c_kernel<<<NROW, 256>>>(C);
    split_wih_kernel<<<NG, 256>>>(Wih);
    wfrag_kernel<<<96, 256>>>(Whh);
    biasc_kernel<<<3, 256>>>(bih, bhh);

    phase1_mma_kernel<<<dim3(NG / BN, NROW / BM), 256, P1_SMEM>>>();

    gru_scan_tc<<<NCTA, SNT, SCN_SMEM>>>(G, bhh, out);
}

// round 15
// speedup vs baseline: 2.1979x; 1.0340x over previous
#include <cuda_runtime.h>
#include <cuda_pipeline.h>
#include <cuda_bf16.h>
#include <cstdint>

// ============================ Problem constants ============================
#define B_TOT 4096
#define SEQ   50
#define HID   256
#define NROW  (B_TOT * SEQ)      // 204800 rows of C (b*50+s)
#define NG    768                // 3 gates * 256
#define KC    768                // concatenated split-K (3 * 256)

// ============================ Device scratch ===============================
__device__ __nv_bfloat16 g_Ccat[(size_t)NROW * KC];   // [row][768] = [Chi|Chi|Clo]
__device__ float         g_gi[(size_t)NROW * NG];     // gi + combined bias
__device__ float         g_biasc[NG];                 // b_ih (+ b_hh for r,z)
// W_hh in mma-B fragment order: tile (kc,nt) = 16x16, one uint4 per lane.
__device__ uint4         g_Wfh[16 * 48 * 32];         // hi split
__device__ uint4         g_Wfl[16 * 48 * 32];         // lo split
// W_ih-concat in mma-B fragment order: (kt*48 + nt)*32 + lane, kt,nt in [0,48)
__device__ uint4         g_Wihf[48 * 48 * 32];

// ============================ helpers ======================================
__device__ __forceinline__ uint32_t smem_u32(const void* p) {
    uint32_t a;
    asm("{ .reg .u64 t; cvta.to.shared.u64 t, %1; cvt.u32.u64 %0, t; }"
        : "=r"(a) : "l"(p));
    return a;
}

#define LDSM_X4(r0, r1, r2, r3, addr) \
    asm volatile("ldmatrix.sync.aligned.m8n8.x4.shared.b16 {%0,%1,%2,%3}, [%4];" \
        : "=r"(r0), "=r"(r1), "=r"(r2), "=r"(r3) : "r"(addr))

#define MMA16816(c, a, b0, b1) \
    asm volatile("mma.sync.aligned.m16n8k16.row.col.f32.bf16.bf16.f32 " \
        "{%0,%1,%2,%3}, {%4,%5,%6,%7}, {%8,%9}, {%0,%1,%2,%3};" \
        : "+f"((c)[0]), "+f"((c)[1]), "+f"((c)[2]), "+f"((c)[3]) \
        : "r"((a)[0]), "r"((a)[1]), "r"((a)[2]), "r"((a)[3]), "r"(b0), "r"(b1))

__device__ __forceinline__ float fast_sigmoid(float x) {
    return __fdividef(1.f, 1.f + __expf(-x));
}
__device__ __forceinline__ float fast_tanh(float x) {
    x = fminf(fmaxf(x, -30.f), 30.f);
    float e = __expf(-2.f * x);
    return __fdividef(1.f - e, 1.f + e);
}

__device__ __forceinline__ uint32_t pk_hi(float a, float b) {
    __nv_bfloat162 h = __floats2bfloat162_rn(a, b);
    return *(uint32_t*)&h;
}
__device__ __forceinline__ uint32_t pk_lo(float a, float b) {
    float ar = a - __bfloat162float(__float2bfloat16(a));
    float br = b - __bfloat162float(__float2bfloat16(b));
    __nv_bfloat162 h = __floats2bfloat162_rn(ar, br);
    return *(uint32_t*)&h;
}

// ============================ Prep kernels =================================
__global__ void split_c_kernel(const float* __restrict__ C) {
    size_t idx = (size_t)blockIdx.x * 256 + threadIdx.x;   // over NROW*HID
    size_t r = idx >> 8;
    int k = (int)(idx & 255);
    float v = C[idx];
    __nv_bfloat16 hi = __float2bfloat16(v);
    __nv_bfloat16 lo = __float2bfloat16(v - __bfloat162float(hi));
    __nv_bfloat16* row = g_Ccat + r * KC;
    row[k] = hi; row[256 + k] = hi; row[512 + k] = lo;
}

// W_ih concat value at (gate g, concat-k), packed with its k+1 neighbor.
// Bands: k<256 -> hi(Wih[g][k]); 256..511 -> lo(Wih[g][k-256]); >=512 -> hi(Wih[g][k-512])
__device__ __forceinline__ uint32_t pk_cat(const float* __restrict__ Wih,
                                           int g, int k) {
    int band = k >> 8, kk = k & 255;
    float v0 = Wih[(size_t)g * HID + kk];
    float v1 = Wih[(size_t)g * HID + kk + 1];
    if (band == 1) return pk_lo(v0, v1);
    return pk_hi(v0, v1);
}

// W_ih-concat -> mma-B fragment order. 48*48 tiles * 32 lanes = 73728 threads.
__global__ void wihfrag_kernel(const float* __restrict__ Wih) {
    int t = blockIdx.x * 256 + threadIdx.x;    // 288 blocks
    int lane = t & 31;
    int tile = t >> 5;                          // kt*48 + nt
    int nt = tile % 48, kt = tile / 48;
    int r  = nt * 16 + (lane >> 2);
    int k0 = kt * 16 + (lane & 3) * 2;
    uint4 v;
    v.x = pk_cat(Wih, r,     k0);
    v.y = pk_cat(Wih, r,     k0 + 8);
    v.z = pk_cat(Wih, r + 8, k0);
    v.w = pk_cat(Wih, r + 8, k0 + 8);
    g_Wihf[t] = v;
}

// W_hh -> mma-B fragment order (hi/lo splits). 24576 lanes.
__global__ void wfrag_kernel(const float* __restrict__ Whh) {
    int t = blockIdx.x * 256 + threadIdx.x;    // 96 blocks
    int lane = t & 31;
    int tile = t >> 5;                          // kc*48 + nt
    int nt = tile % 48, kc = tile / 48;
    int r  = nt * 16 + (lane >> 2);
    int k0 = kc * 16 + (lane & 3) * 2;
    const float* w0 = Whh + (size_t)r * HID;
    const float* w8 = Whh + (size_t)(r + 8) * HID;
    float a0 = w0[k0], a1 = w0[k0 + 1], a8 = w0[k0 + 8], a9 = w0[k0 + 9];
    float b0 = w8[k0], b1 = w8[k0 + 1], b8 = w8[k0 + 8], b9 = w8[k0 + 9];
    uint4 vh, vl;
    vh.x = pk_hi(a0, a1); vh.y = pk_hi(a8, a9);
    vh.z = pk_hi(b0, b1); vh.w = pk_hi(b8, b9);
    vl.x = pk_lo(a0, a1); vl.y = pk_lo(a8, a9);
    vl.z = pk_lo(b0, b1); vl.w = pk_lo(b8, b9);
    g_Wfh[t] = vh;
    g_Wfl[t] = vl;
}

__global__ void biasc_kernel(const float* __restrict__ bih,
                             const float* __restrict__ bhh) {
    int n = blockIdx.x * 256 + threadIdx.x;                // 3 blocks
    g_biasc[n] = bih[n] + (n < 512 ? bhh[n] : 0.f);
}

// ============================ Phase 1: gi GEMM (mma.sync) ==================
// A via cp.async smem + LDSM (HBM stream); B via fragment LDG (L2-resident).
#define BM 128
#define BN 128
#define BK 64
#define NCHUNK (KC / BK)          // 12
#define PITCH  72                 // bf16 elems per smem row (144B = 9*16B)
#define ATILE  (BM * PITCH)
#define P1_SMEM (2 * ATILE * 2)   // 36864 (A double buffer only)

__device__ __forceinline__ void p1_load_a(__nv_bfloat16* adst,
                                          const __nv_bfloat16* asrc, int tid) {
    #pragma unroll
    for (int q = 0; q < 4; ++q) {
        int i = q * 256 + tid;
        int row = i >> 3, seg = i & 7;
        __pipeline_memcpy_async(adst + row * PITCH + seg * 8,
                                asrc + (size_t)row * KC + seg * 8, 16);
    }
    __pipeline_commit();
}

__global__ void __launch_bounds__(256, 2)
phase1_mma_kernel() {
    extern __shared__ __nv_bfloat16 sh[];
    const int tid  = threadIdx.x;
    const int lane = tid & 31;
    const int wid  = tid >> 5;
    const int wm   = wid & 1;
    const int wn   = wid >> 1;
    const int n0   = blockIdx.x * BN;
    const size_t m0 = (size_t)blockIdx.y * BM;

    __nv_bfloat16* Abuf[2] = { sh, sh + ATILE };

    float c[4][4][4];
    #pragma unroll
    for (int i = 0; i < 4; ++i)
        #pragma unroll
        for (int j = 0; j < 4; ++j)
            #pragma unroll
            for (int q = 0; q < 4; ++q) c[i][j][q] = 0.f;

    const __nv_bfloat16* asrc0 = g_Ccat + m0 * KC;
    p1_load_a(Abuf[0], asrc0, tid);

    const int a_row  = wm * 64 + (lane & 15);
    const int a_colp = (lane >> 4) * 8;
    const int ntb    = (n0 >> 4) + wn * 2;     // this warp's 2 n16 tiles

    // B ring of 2 (slot = kt & 1, compile-time inside unrolled ks loop)
    uint4 bf[2][2];
    #pragma unroll
    for (int pi = 0; pi < 2; ++pi)
        #pragma unroll
        for (int t2 = 0; t2 < 2; ++t2)
            bf[pi][t2] = g_Wihf[((size_t)pi * 48 + ntb + t2) * 32 + lane];

    #pragma unroll 1
    for (int ch = 0; ch < NCHUNK; ++ch) {
        if (ch + 1 < NCHUNK)
            p1_load_a(Abuf[(ch + 1) & 1], asrc0 + (ch + 1) * BK, tid);
        __pipeline_wait_prior((ch + 1 < NCHUNK) ? 1 : 0);
        __syncthreads();

        const uint32_t abase = smem_u32(Abuf[ch & 1]);

        #pragma unroll
        for (int ks = 0; ks < 4; ++ks) {
            const int kt = ch * 4 + ks;
            const int p  = ks & 1;            // == kt & 1
            uint32_t a[4][4];
            #pragma unroll
            for (int mi = 0; mi < 4; ++mi) {
                uint32_t addr = abase +
                    ((a_row + mi * 16) * PITCH + ks * 16 + a_colp) * 2;
                LDSM_X4(a[mi][0], a[mi][1], a[mi][2], a[mi][3], addr);
            }
            #pragma unroll
            for (int t2 = 0; t2 < 2; ++t2) {
                #pragma unroll
                for (int mi = 0; mi < 4; ++mi) {
                    MMA16816(c[mi][t2 * 2],     a[mi], bf[p][t2].x, bf[p][t2].y);
                    MMA16816(c[mi][t2 * 2 + 1], a[mi], bf[p][t2].z, bf[p][t2].w);
                }
            }
            // refill slot p with kt+2 (wraps harmlessly at the end)
            {
                const int ktn = (kt + 2) % 48;
                #pragma unroll
                for (int t2 = 0; t2 < 2; ++t2)
                    bf[p][t2] = g_Wihf[((size_t)ktn * 48 + ntb + t2) * 32 + lane];
            }
        }
        __syncthreads();
    }

    // epilogue: add combined bias, store
    const int r_base = (int)(wm * 64) + (lane >> 2);
    const int c_base = n0 + wn * 32 + (lane & 3) * 2;
    #pragma unroll
    for (int ni = 0; ni < 4; ++ni) {
        int col = c_base + ni * 8;
        float2 bv = *(const float2*)&g_biasc[col];
        #pragma unroll
        for (int mi = 0; mi < 4; ++mi) {
            size_t row = m0 + r_base + mi * 16;
            *(float2*)&g_gi[row * NG + col] =
                make_float2(c[mi][ni][0] + bv.x, c[mi][ni][1] + bv.y);
            *(float2*)&g_gi[(row + 8) * NG + col] =
                make_float2(c[mi][ni][2] + bv.x, c[mi][ni][3] + bv.y);
        }
    }
}

// ============================ Phase 2: tensor-core scan ====================
// B fragments via LDG from L2-resident g_Wfh/g_Wfl; ring of 3 slots (slot=g3),
// reload (kc+1, g3) right after use -> 3-stage (~290cyc) lookahead. W preload
// hoisted out of the step loop (W is step-invariant).
#define TB    32
#define NCTA  (B_TOT / TB)        // 128
#define SNT   256
#define SPA   264                 // A pitch (elems), 528B = 33*16B
#define SPH   260                 // h pitch (floats)

#define OFF_AHI 0                                   // 32*264*2 = 16896
#define OFF_ALO (OFF_AHI + 32 * SPA * 2)            // 16896
#define OFF_H   (OFF_ALO + 32 * SPA * 2)            // 33792, 32*260*4 = 33280
#define OFF_BHN (OFF_H + 32 * SPH * 4)              // 67072, 1024
#define OFF_G   (OFF_BHN + 256 * 4)                 // 68096, 128
#define SCN_SMEM (OFF_G + 32 * 4)                   // 68224

__global__ void __launch_bounds__(SNT, 1)
gru_scan_tc(const float* __restrict__ G, const float* __restrict__ b_hh,
            float* __restrict__ out)
{
    extern __shared__ char smp[];
    const int tid  = threadIdx.x;
    const int lane = tid & 31;
    const int w    = tid >> 5;                 // 8 warps, each owns 3x32 n-cols
    const int bbase = blockIdx.x * TB;
    const int qrow = lane >> 2;
    const int qcol = (lane & 3) * 2;

    float* hS   = (float*)(smp + OFF_H);
    float* bhnS = (float*)(smp + OFF_BHN);
    float* gS   = (float*)(smp + OFF_G);

    for (int i = tid; i < 32 * SPH; i += SNT) hS[i] = 0.f;
    bhnS[tid] = b_hh[512 + tid];
    __syncthreads();

    // constant n-gate bias fragments
    float2 bnv[4];
    #pragma unroll
    for (int ni = 0; ni < 4; ++ni)
        bnv[ni] = *(const float2*)&bhnS[32 * w + 8 * ni + qcol];

    const uint32_t ahi_base = smem_u32(smp + OFF_AHI);
    const uint32_t alo_base = smem_u32(smp + OFF_ALO);
    const int arow = lane & 15;
    const int acp  = (lane >> 4) * 8;
    const int wf_lane = 2 * w * 32 + lane;     // lane offset within (kc,g3) row

    // ---- B ring preload: slot g3 holds stage (kc=0, g3) ----
    uint4 bh[3][2], bl[3][2];
    #pragma unroll
    for (int pi = 0; pi < 3; ++pi) {
        const int base = (pi * 16) * 32;       // kc=0, nt base = g3*16
        #pragma unroll
        for (int t2 = 0; t2 < 2; ++t2) {
            bh[pi][t2] = g_Wfh[base + wf_lane + t2 * 32];
            bl[pi][t2] = g_Wfl[base + wf_lane + t2 * 32];
        }
    }

    #pragma unroll 1
    for (int s = 0; s < SEQ; ++s) {
        // ---- gi loads (issued early) + gate G ----
        float2 gr[2][4], gz[2][4], gnv[2][4];
        #pragma unroll
        for (int mi = 0; mi < 2; ++mi) {
            size_t r0 = ((size_t)(bbase + 16 * mi + qrow) * SEQ + s) * NG;
            size_t r1 = r0 + (size_t)8 * SEQ * NG;
            #pragma unroll
            for (int ni = 0; ni < 4; ++ni) {
                int col = 32 * w + 8 * ni + qcol;
                gr[mi][ni]  = make_float2(g_gi[r0 + col],       g_gi[r1 + col]);
                gz[mi][ni]  = make_float2(g_gi[r0 + 256 + col], g_gi[r1 + 256 + col]);
                gnv[mi][ni] = make_float2(g_gi[r0 + 512 + col], g_gi[r1 + 512 + col]);
            }
        }
        if (tid < TB) gS[tid] = G[(size_t)(bbase + tid) * SEQ + s];

        // ---- convert h fp32 -> A_hi/A_lo bf16 ----
        {
            int b = tid >> 3, kb = (tid & 7) * 32;
            const float* hr = hS + b * SPH + kb;
            __nv_bfloat16* AH = (__nv_bfloat16*)(smp + OFF_AHI) + b * SPA + kb;
            __nv_bfloat16* AL = (__nv_bfloat16*)(smp + OFF_ALO) + b * SPA + kb;
            #pragma unroll
            for (int i = 0; i < 8; ++i) {
                float4 v = *(const float4*)(hr + 4 * i);
                __nv_bfloat16 h0 = __float2bfloat16(v.x);
                __nv_bfloat16 h1 = __float2bfloat16(v.y);
                __nv_bfloat16 h2 = __float2bfloat16(v.z);
                __nv_bfloat16 h3 = __float2bfloat16(v.w);
                __nv_bfloat16 l0 = __float2bfloat16(v.x - __bfloat162float(h0));
                __nv_bfloat16 l1 = __float2bfloat16(v.y - __bfloat162float(h1));
                __nv_bfloat16 l2 = __float2bfloat16(v.z - __bfloat162float(h2));
                __nv_bfloat16 l3 = __float2bfloat16(v.w - __bfloat162float(h3));
                *(__nv_bfloat162*)(AH + 4 * i)     = __halves2bfloat162(h0, h1);
                *(__nv_bfloat162*)(AH + 4 * i + 2) = __halves2bfloat162(h2, h3);
                *(__nv_bfloat162*)(AL + 4 * i)     = __halves2bfloat162(l0, l1);
                *(__nv_bfloat162*)(AL + 4 * i + 2) = __halves2bfloat162(l2, l3);
            }
        }
        __syncthreads();

        // ---- init accumulators ----
        float c[2][12][4];
        float gin[2][4][4];
        #pragma unroll
        for (int mi = 0; mi < 2; ++mi)
            #pragma unroll
            for (int ni = 0; ni < 4; ++ni) {
                c[mi][ni][0] = gr[mi][ni].x;     c[mi][ni][1] = 0.f;
                c[mi][ni][2] = gr[mi][ni].y;     c[mi][ni][3] = 0.f;
                c[mi][ni + 4][0] = gz[mi][ni].x; c[mi][ni + 4][1] = 0.f;
                c[mi][ni + 4][2] = gz[mi][ni].y; c[mi][ni + 4][3] = 0.f;
                gin[mi][ni][0] = gnv[mi][ni].x;  gin[mi][ni][2] = gnv[mi][ni].y;
                c[mi][ni + 8][0] = bnv[ni].x;    c[mi][ni + 8][1] = bnv[ni].y;
                c[mi][ni + 8][2] = bnv[ni].x;    c[mi][ni + 8][3] = bnv[ni].y;
            }
        // odd-column gi elements
        #pragma unroll
        for (int mi = 0; mi < 2; ++mi) {
            size_t r0 = ((size_t)(bbase + 16 * mi + qrow) * SEQ + s) * NG;
            size_t r1 = r0 + (size_t)8 * SEQ * NG;
            #pragma unroll
            for (int ni = 0; ni < 4; ++ni) {
                int col = 32 * w + 8 * ni + qcol;
                c[mi][ni][1] = g_gi[r0 + col + 1];
                c[mi][ni][3] = g_gi[r1 + col + 1];
                c[mi][ni + 4][1] = g_gi[r0 + 256 + col + 1];
                c[mi][ni + 4][3] = g_gi[r1 + 256 + col + 1];
                gin[mi][ni][1] = g_gi[r0 + 512 + col + 1];
                gin[mi][ni][3] = g_gi[r1 + 512 + col + 1];
            }
        }

        // ---- K loop: 16 kc x 3 gates; slot g3 reloaded with (kc+1, g3) ----
        #pragma unroll
        for (int kc = 0; kc < 16; ++kc) {
            uint32_t ah[2][4], al4[2][4];
            #pragma unroll
            for (int mi = 0; mi < 2; ++mi) {
                uint32_t addr = ahi_base +
                    ((arow + 16 * mi) * SPA + kc * 16 + acp) * 2;
                LDSM_X4(ah[mi][0], ah[mi][1], ah[mi][2], ah[mi][3], addr);
                addr = alo_base + ((arow + 16 * mi) * SPA + kc * 16 + acp) * 2;
                LDSM_X4(al4[mi][0], al4[mi][1], al4[mi][2], al4[mi][3], addr);
            }
            #pragma unroll
            for (int g3 = 0; g3 < 3; ++g3) {
                // term 1: h_hi * W_hi  (8 independent accumulators)
                #pragma unroll
                for (int mi = 0; mi < 2; ++mi)
                    #pragma unroll
                    for (int t2 = 0; t2 < 2; ++t2) {
                        MMA16816(c[mi][4 * g3 + 2 * t2],     ah[mi], bh[g3][t2].x, bh[g3][t2].y);
                        MMA16816(c[mi][4 * g3 + 2 * t2 + 1], ah[mi], bh[g3][t2].z, bh[g3][t2].w);
                    }
                // term 2: h_lo * W_hi
                #pragma unroll
                for (int mi = 0; mi < 2; ++mi)
                    #pragma unroll
                    for (int t2 = 0; t2 < 2; ++t2) {
                        MMA16816(c[mi][4 * g3 + 2 * t2],     al4[mi], bh[g3][t2].x, bh[g3][t2].y);
                        MMA16816(c[mi][4 * g3 + 2 * t2 + 1], al4[mi], bh[g3][t2].z, bh[g3][t2].w);
                    }
                // term 3: h_hi * W_lo
                #pragma unroll
                for (int mi = 0; mi < 2; ++mi)
                    #pragma unroll
                    for (int t2 = 0; t2 < 2; ++t2) {
                        MMA16816(c[mi][4 * g3 + 2 * t2],     ah[mi], bl[g3][t2].x, bl[g3][t2].y);
                        MMA16816(c[mi][4 * g3 + 2 * t2 + 1], ah[mi], bl[g3][t2].z, bl[g3][t2].w);
                    }
                // refill slot g3 with (kc+1 mod 16, g3) -> ready next kc
                {
                    const int base = ((((kc + 1) & 15) * 48) + g3 * 16) * 32;
                    #pragma unroll
                    for (int t2 = 0; t2 < 2; ++t2) {
                        bh[g3][t2] = g_Wfh[base + wf_lane + t2 * 32];
                        bl[g3][t2] = g_Wfl[base + wf_lane + t2 * 32];
                    }
                }
            }
        }

        // ---- epilogue: gates + gated h update (thread-local positions) ----
        #pragma unroll
        for (int mi = 0; mi < 2; ++mi) {
            #pragma unroll
            for (int ni = 0; ni < 4; ++ni) {
                int j = 32 * w + 8 * ni + qcol;
                #pragma unroll
                for (int rh = 0; rh < 2; ++rh) {
                    int b = 16 * mi + qrow + 8 * rh;
                    float g = gS[b];
                    float2 hp = *(const float2*)&hS[b * SPH + j];
                    float res[2];
                    #pragma unroll
                    for (int q2 = 0; q2 < 2; ++q2) {
                        int q = 2 * rh + q2;
                        float r = fast_sigmoid(c[mi][ni][q]);
                        float z = fast_sigmoid(c[mi][ni + 4][q]);
                        float hn = c[mi][ni + 8][q];         // h·Whn + b_hh_n
                        float n = fast_tanh(gin[mi][ni][q] + r * hn);
                        float hprev = q2 ? hp.y : hp.x;
                        float hnew = (1.f - z) * n + z * hprev;
                        res[q2] = g * hnew + (1.f - g) * hprev;
                    }
                    *(float2*)&hS[b * SPH + j] = make_float2(res[0], res[1]);
                }
            }
        }
        __syncthreads();
    }

    // ---- final output ----
    #pragma unroll 1
    for (int r = 0; r < TB; ++r)
        out[(size_t)(bbase + r) * HID + tid] = hS[r * SPH + tid];
}

// ============================ Launch =======================================
extern "C" void kernel_launch(void* const* d_in, const int* in_sizes, int n_in,
                              void* d_out, int out_size) {
    const float* C   = (const float*)d_in[0];
    const float* G   = (const float*)d_in[1];
    const float* Wih = (const float*)d_in[2];
    const float* Whh = (const float*)d_in[3];
    const float* bih = (const float*)d_in[4];
    const float* bhh = (const float*)d_in[5];
    float* out = (float*)d_out;

    cudaFuncSetAttribute(phase1_mma_kernel,
                         cudaFuncAttributeMaxDynamicSharedMemorySize, P1_SMEM);
    cudaFuncSetAttribute(gru_scan_tc,
                         cudaFuncAttributeMaxDynamicSharedMemorySize, SCN_SMEM);

    split_c_kernel<<<NROW, 256>>>(C);
    wihfrag_kernel<<<288, 256>>>(Wih);
    wfrag_kernel<<<96, 256>>>(Whh);
    biasc_kernel<<<3, 256>>>(bih, bhh);

    phase1_mma_kernel<<<dim3(NG / BN, NROW / BM), 256, P1_SMEM>>>();

    gru_scan_tc<<<NCTA, SNT, SCN_SMEM>>>(G, bhh, out);
}

// round 16
// speedup vs baseline: 2.4078x; 1.0955x over previous
#include <cuda_runtime.h>
#include <cuda_pipeline.h>
#include <cuda_bf16.h>
#include <cstdint>

// ============================ Problem constants ============================
#define B_TOT 4096
#define SEQ   50
#define HID   256
#define NROW  (B_TOT * SEQ)      // 204800 rows of C (b*50+s)
#define NG    768                // 3 gates * 256
#define KC2   512                // [Chi|Clo] split-K

// ============================ Device scratch ===============================
__device__ __nv_bfloat16 g_Ccat[(size_t)NROW * KC2];  // [row][512] = [Chi|Clo]
__device__ float         g_gi[(size_t)NROW * NG];     // gi + combined bias
__device__ float         g_biasc[NG];                 // b_ih (+ b_hh for r,z)
// W in mma-B fragment order: tile (kc,nt) = 16x16, one uint4 per lane.
// index = (kc*48 + nt)*32 + lane,  kc in [0,16), nt in [0,48)
__device__ uint4         g_Wfh[16 * 48 * 32];         // W_hh hi split
__device__ uint4         g_Wfl[16 * 48 * 32];         // W_hh lo split
__device__ uint4         g_Wihfh[16 * 48 * 32];       // W_ih hi split
__device__ uint4         g_Wihfl[16 * 48 * 32];       // W_ih lo split

// ============================ helpers ======================================
__device__ __forceinline__ uint32_t smem_u32(const void* p) {
    uint32_t a;
    asm("{ .reg .u64 t; cvta.to.shared.u64 t, %1; cvt.u32.u64 %0, t; }"
        : "=r"(a) : "l"(p));
    return a;
}

#define LDSM_X4(r0, r1, r2, r3, addr) \
    asm volatile("ldmatrix.sync.aligned.m8n8.x4.shared.b16 {%0,%1,%2,%3}, [%4];" \
        : "=r"(r0), "=r"(r1), "=r"(r2), "=r"(r3) : "r"(addr))

#define MMA16816(c, a, b0, b1) \
    asm volatile("mma.sync.aligned.m16n8k16.row.col.f32.bf16.bf16.f32 " \
        "{%0,%1,%2,%3}, {%4,%5,%6,%7}, {%8,%9}, {%0,%1,%2,%3};" \
        : "+f"((c)[0]), "+f"((c)[1]), "+f"((c)[2]), "+f"((c)[3]) \
        : "r"((a)[0]), "r"((a)[1]), "r"((a)[2]), "r"((a)[3]), "r"(b0), "r"(b1))

__device__ __forceinline__ float fast_sigmoid(float x) {
    return __fdividef(1.f, 1.f + __expf(-x));
}
__device__ __forceinline__ float fast_tanh(float x) {
    x = fminf(fmaxf(x, -30.f), 30.f);
    float e = __expf(-2.f * x);
    return __fdividef(1.f - e, 1.f + e);
}

__device__ __forceinline__ uint32_t pk_hi(float a, float b) {
    __nv_bfloat162 h = __floats2bfloat162_rn(a, b);
    return *(uint32_t*)&h;
}
__device__ __forceinline__ uint32_t pk_lo(float a, float b) {
    float ar = a - __bfloat162float(__float2bfloat16(a));
    float br = b - __bfloat162float(__float2bfloat16(b));
    __nv_bfloat162 h = __floats2bfloat162_rn(ar, br);
    return *(uint32_t*)&h;
}

// ============================ Prep kernels =================================
__global__ void split_c_kernel(const float* __restrict__ C) {
    size_t idx = (size_t)blockIdx.x * 256 + threadIdx.x;   // over NROW*HID
    size_t r = idx >> 8;
    int k = (int)(idx & 255);
    float v = C[idx];
    __nv_bfloat16 hi = __float2bfloat16(v);
    __nv_bfloat16 lo = __float2bfloat16(v - __bfloat162float(hi));
    __nv_bfloat16* row = g_Ccat + r * KC2;
    row[k] = hi; row[256 + k] = lo;
}

// W[768][256] -> mma-B fragment order, hi/lo splits. which: 0 = W_hh, 1 = W_ih
__global__ void wfrag_kernel(const float* __restrict__ W, int which) {
    int t = blockIdx.x * 256 + threadIdx.x;    // 96 blocks * 256 = 24576
    int lane = t & 31;
    int tile = t >> 5;                          // kc*48 + nt
    int nt = tile % 48, kc = tile / 48;
    int r  = nt * 16 + (lane >> 2);
    int k0 = kc * 16 + (lane & 3) * 2;
    const float* w0 = W + (size_t)r * HID;
    const float* w8 = W + (size_t)(r + 8) * HID;
    float a0 = w0[k0], a1 = w0[k0 + 1], a8 = w0[k0 + 8], a9 = w0[k0 + 9];
    float b0 = w8[k0], b1 = w8[k0 + 1], b8 = w8[k0 + 8], b9 = w8[k0 + 9];
    uint4 vh, vl;
    vh.x = pk_hi(a0, a1); vh.y = pk_hi(a8, a9);
    vh.z = pk_hi(b0, b1); vh.w = pk_hi(b8, b9);
    vl.x = pk_lo(a0, a1); vl.y = pk_lo(a8, a9);
    vl.z = pk_lo(b0, b1); vl.w = pk_lo(b8, b9);
    if (which) { g_Wihfh[t] = vh; g_Wihfl[t] = vl; }
    else       { g_Wfh[t]   = vh; g_Wfl[t]   = vl; }
}

__global__ void biasc_kernel(const float* __restrict__ bih,
                             const float* __restrict__ bhh) {
    int n = blockIdx.x * 256 + threadIdx.x;                // 3 blocks
    g_biasc[n] = bih[n] + (n < 512 ? bhh[n] : 0.f);
}

// ============================ Phase 1: gi GEMM (mma.sync) ==================
// A = [Chi|Clo] K=512 via cp.async smem + LDSM; B via fragment LDG (L2).
// hi band (kt 0..15): c += a*Whi; c += a*Wlo.   lo band (kt 16..31): c += a*Whi.
#define BM 128
#define BN 128
#define BK 64
#define NCHUNK (KC2 / BK)         // 8
#define PITCH  72                 // bf16 elems per smem row (144B = 9*16B)
#define ATILE  (BM * PITCH)
#define P1_SMEM (2 * ATILE * 2)   // 36864 (A double buffer only)

__device__ __forceinline__ void p1_load_a(__nv_bfloat16* adst,
                                          const __nv_bfloat16* asrc, int tid) {
    #pragma unroll
    for (int q = 0; q < 4; ++q) {
        int i = q * 256 + tid;
        int row = i >> 3, seg = i & 7;
        __pipeline_memcpy_async(adst + row * PITCH + seg * 8,
                                asrc + (size_t)row * KC2 + seg * 8, 16);
    }
    __pipeline_commit();
}

__global__ void __launch_bounds__(256, 2)
phase1_mma_kernel() {
    extern __shared__ __nv_bfloat16 sh[];
    const int tid  = threadIdx.x;
    const int lane = tid & 31;
    const int wid  = tid >> 5;
    const int wm   = wid & 1;
    const int wn   = wid >> 1;
    const int n0   = blockIdx.x * BN;
    const size_t m0 = (size_t)blockIdx.y * BM;

    __nv_bfloat16* Abuf[2] = { sh, sh + ATILE };

    float c[4][4][4];
    #pragma unroll
    for (int i = 0; i < 4; ++i)
        #pragma unroll
        for (int j = 0; j < 4; ++j)
            #pragma unroll
            for (int q = 0; q < 4; ++q) c[i][j][q] = 0.f;

    const __nv_bfloat16* asrc0 = g_Ccat + m0 * KC2;
    p1_load_a(Abuf[0], asrc0, tid);

    const int a_row  = wm * 64 + (lane & 15);
    const int a_colp = (lane >> 4) * 8;
    const int ntb    = (n0 >> 4) + wn * 2;     // this warp's 2 n16 tiles

    // B ring of 2 (slot = kt & 1); preload kt = 0, 1 (hi band)
    uint4 bfh[2][2], bfl[2][2];
    #pragma unroll
    for (int pi = 0; pi < 2; ++pi)
        #pragma unroll
        for (int t2 = 0; t2 < 2; ++t2) {
            bfh[pi][t2] = g_Wihfh[((size_t)pi * 48 + ntb + t2) * 32 + lane];
            bfl[pi][t2] = g_Wihfl[((size_t)pi * 48 + ntb + t2) * 32 + lane];
        }

    // ---- hi band: chunks 0..3 (kt 0..15), 2 MMAs per kt ----
    #pragma unroll 1
    for (int ch = 0; ch < 4; ++ch) {
        p1_load_a(Abuf[(ch + 1) & 1], asrc0 + (ch + 1) * BK, tid);
        __pipeline_wait_prior(1);
        __syncthreads();
        const uint32_t abase = smem_u32(Abuf[ch & 1]);
        #pragma unroll
        for (int ks = 0; ks < 4; ++ks) {
            const int kt = ch * 4 + ks;
            const int p  = ks & 1;
            uint32_t a[4][4];
            #pragma unroll
            for (int mi = 0; mi < 4; ++mi) {
                uint32_t addr = abase +
                    ((a_row + mi * 16) * PITCH + ks * 16 + a_colp) * 2;
                LDSM_X4(a[mi][0], a[mi][1], a[mi][2], a[mi][3], addr);
            }
            #pragma unroll
            for (int t2 = 0; t2 < 2; ++t2)
                #pragma unroll
                for (int mi = 0; mi < 4; ++mi) {
                    MMA16816(c[mi][t2 * 2],     a[mi], bfh[p][t2].x, bfh[p][t2].y);
                    MMA16816(c[mi][t2 * 2 + 1], a[mi], bfh[p][t2].z, bfh[p][t2].w);
                }
            #pragma unroll
            for (int t2 = 0; t2 < 2; ++t2)
                #pragma unroll
                for (int mi = 0; mi < 4; ++mi) {
                    MMA16816(c[mi][t2 * 2],     a[mi], bfl[p][t2].x, bfl[p][t2].y);
                    MMA16816(c[mi][t2 * 2 + 1], a[mi], bfl[p][t2].z, bfl[p][t2].w);
                }
            // refill slot p with kt+2
            {
                const int ktn = kt + 2;
                if (ktn < 16) {
                    #pragma unroll
                    for (int t2 = 0; t2 < 2; ++t2) {
                        bfh[p][t2] = g_Wihfh[((size_t)ktn * 48 + ntb + t2) * 32 + lane];
                        bfl[p][t2] = g_Wihfl[((size_t)ktn * 48 + ntb + t2) * 32 + lane];
                    }
                } else {    // ktn = 16,17 -> lo band uses W_hi frags only
                    #pragma unroll
                    for (int t2 = 0; t2 < 2; ++t2)
                        bfh[p][t2] = g_Wihfh[((size_t)(ktn - 16) * 48 + ntb + t2) * 32 + lane];
                }
            }
        }
        __syncthreads();
    }

    // ---- lo band: chunks 4..7 (kt 16..31), 1 MMA per kt ----
    #pragma unroll 1
    for (int ch = 4; ch < 8; ++ch) {
        if (ch + 1 < 8)
            p1_load_a(Abuf[(ch + 1) & 1], asrc0 + (ch + 1) * BK, tid);
        __pipeline_wait_prior((ch + 1 < 8) ? 1 : 0);
        __syncthreads();
        const uint32_t abase = smem_u32(Abuf[ch & 1]);
        #pragma unroll
        for (int ks = 0; ks < 4; ++ks) {
            const int kt = ch * 4 + ks;
            const int p  = ks & 1;
            uint32_t a[4][4];
            #pragma unroll
            for (int mi = 0; mi < 4; ++mi) {
                uint32_t addr = abase +
                    ((a_row + mi * 16) * PITCH + ks * 16 + a_colp) * 2;
                LDSM_X4(a[mi][0], a[mi][1], a[mi][2], a[mi][3], addr);
            }
            #pragma unroll
            for (int t2 = 0; t2 < 2; ++t2)
                #pragma unroll
                for (int mi = 0; mi < 4; ++mi) {
                    MMA16816(c[mi][t2 * 2],     a[mi], bfh[p][t2].x, bfh[p][t2].y);
                    MMA16816(c[mi][t2 * 2 + 1], a[mi], bfh[p][t2].z, bfh[p][t2].w);
                }
            {
                const int ktn = kt + 2;
                if (ktn < 32) {
                    #pragma unroll
                    for (int t2 = 0; t2 < 2; ++t2)
                        bfh[p][t2] = g_Wihfh[((size_t)(ktn - 16) * 48 + ntb + t2) * 32 + lane];
                }
            }
        }
        __syncthreads();
    }

    // epilogue: add combined bias, store
    const int r_base = (int)(wm * 64) + (lane >> 2);
    const int c_base = n0 + wn * 32 + (lane & 3) * 2;
    #pragma unroll
    for (int ni = 0; ni < 4; ++ni) {
        int col = c_base + ni * 8;
        float2 bv = *(const float2*)&g_biasc[col];
        #pragma unroll
        for (int mi = 0; mi < 4; ++mi) {
            size_t row = m0 + r_base + mi * 16;
            *(float2*)&g_gi[row * NG + col] =
                make_float2(c[mi][ni][0] + bv.x, c[mi][ni][1] + bv.y);
            *(float2*)&g_gi[(row + 8) * NG + col] =
                make_float2(c[mi][ni][2] + bv.x, c[mi][ni][3] + bv.y);
        }
    }
}

// ============================ Phase 2: tensor-core scan ====================
#define TB    32
#define NCTA  (B_TOT / TB)        // 128
#define SNT   256
#define SPA   264                 // A pitch (elems), 528B = 33*16B
#define SPH   260                 // h pitch (floats)

#define OFF_AHI 0                                   // 32*264*2 = 16896
#define OFF_ALO (OFF_AHI + 32 * SPA * 2)            // 16896
#define OFF_H   (OFF_ALO + 32 * SPA * 2)            // 33792, 32*260*4 = 33280
#define OFF_BHN (OFF_H + 32 * SPH * 4)              // 67072, 1024
#define OFF_G   (OFF_BHN + 256 * 4)                 // 68096, 128
#define SCN_SMEM (OFF_G + 32 * 4)                   // 68224

__global__ void __launch_bounds__(SNT, 1)
gru_scan_tc(const float* __restrict__ G, const float* __restrict__ b_hh,
            float* __restrict__ out)
{
    extern __shared__ char smp[];
    const int tid  = threadIdx.x;
    const int lane = tid & 31;
    const int w    = tid >> 5;                 // 8 warps, each owns 3x32 n-cols
    const int bbase = blockIdx.x * TB;
    const int qrow = lane >> 2;
    const int qcol = (lane & 3) * 2;

    float* hS   = (float*)(smp + OFF_H);
    float* bhnS = (float*)(smp + OFF_BHN);
    float* gS   = (float*)(smp + OFF_G);

    for (int i = tid; i < 32 * SPH; i += SNT) hS[i] = 0.f;
    bhnS[tid] = b_hh[512 + tid];
    __syncthreads();

    float2 bnv[4];
    #pragma unroll
    for (int ni = 0; ni < 4; ++ni)
        bnv[ni] = *(const float2*)&bhnS[32 * w + 8 * ni + qcol];

    const uint32_t ahi_base = smem_u32(smp + OFF_AHI);
    const uint32_t alo_base = smem_u32(smp + OFF_ALO);
    const int arow = lane & 15;
    const int acp  = (lane >> 4) * 8;
    const int wf_lane = 2 * w * 32 + lane;

    // ---- B ring preload: slot g3 holds stage (kc=0, g3) ----
    uint4 bh[3][2], bl[3][2];
    #pragma unroll
    for (int pi = 0; pi < 3; ++pi) {
        const int base = (pi * 16) * 32;
        #pragma unroll
        for (int t2 = 0; t2 < 2; ++t2) {
            bh[pi][t2] = g_Wfh[base + wf_lane + t2 * 32];
            bl[pi][t2] = g_Wfl[base + wf_lane + t2 * 32];
        }
    }

    #pragma unroll 1
    for (int s = 0; s < SEQ; ++s) {
        // ---- accumulator init: aligned float2 gi loads (issued first) ----
        float c[2][12][4];
        float gin[2][4][4];
        #pragma unroll
        for (int mi = 0; mi < 2; ++mi) {
            size_t r0 = ((size_t)(bbase + 16 * mi + qrow) * SEQ + s) * NG;
            size_t r1 = r0 + (size_t)8 * SEQ * NG;
            #pragma unroll
            for (int ni = 0; ni < 4; ++ni) {
                int col = 32 * w + 8 * ni + qcol;
                float2 a0 = *(const float2*)&g_gi[r0 + col];
                float2 a1 = *(const float2*)&g_gi[r1 + col];
                float2 z0 = *(const float2*)&g_gi[r0 + 256 + col];
                float2 z1 = *(const float2*)&g_gi[r1 + 256 + col];
                float2 n0 = *(const float2*)&g_gi[r0 + 512 + col];
                float2 n1 = *(const float2*)&g_gi[r1 + 512 + col];
                c[mi][ni][0] = a0.x;  c[mi][ni][1] = a0.y;
                c[mi][ni][2] = a1.x;  c[mi][ni][3] = a1.y;
                c[mi][ni + 4][0] = z0.x;  c[mi][ni + 4][1] = z0.y;
                c[mi][ni + 4][2] = z1.x;  c[mi][ni + 4][3] = z1.y;
                gin[mi][ni][0] = n0.x;  gin[mi][ni][1] = n0.y;
                gin[mi][ni][2] = n1.x;  gin[mi][ni][3] = n1.y;
                c[mi][ni + 8][0] = bnv[ni].x;  c[mi][ni + 8][1] = bnv[ni].y;
                c[mi][ni + 8][2] = bnv[ni].x;  c[mi][ni + 8][3] = bnv[ni].y;
            }
        }
        if (tid < TB) gS[tid] = G[(size_t)(bbase + tid) * SEQ + s];

        // ---- convert h fp32 -> A_hi/A_lo bf16 (hides gi load latency) ----
        {
            int b = tid >> 3, kb = (tid & 7) * 32;
            const float* hr = hS + b * SPH + kb;
            __nv_bfloat16* AH = (__nv_bfloat16*)(smp + OFF_AHI) + b * SPA + kb;
            __nv_bfloat16* AL = (__nv_bfloat16*)(smp + OFF_ALO) + b * SPA + kb;
            #pragma unroll
            for (int i = 0; i < 8; ++i) {
                float4 v = *(const float4*)(hr + 4 * i);
                __nv_bfloat16 h0 = __float2bfloat16(v.x);
                __nv_bfloat16 h1 = __float2bfloat16(v.y);
                __nv_bfloat16 h2 = __float2bfloat16(v.z);
                __nv_bfloat16 h3 = __float2bfloat16(v.w);
                __nv_bfloat16 l0 = __float2bfloat16(v.x - __bfloat162float(h0));
                __nv_bfloat16 l1 = __float2bfloat16(v.y - __bfloat162float(h1));
                __nv_bfloat16 l2 = __float2bfloat16(v.z - __bfloat162float(h2));
                __nv_bfloat16 l3 = __float2bfloat16(v.w - __bfloat162float(h3));
                *(__nv_bfloat162*)(AH + 4 * i)     = __halves2bfloat162(h0, h1);
                *(__nv_bfloat162*)(AH + 4 * i + 2) = __halves2bfloat162(h2, h3);
                *(__nv_bfloat162*)(AL + 4 * i)     = __halves2bfloat162(l0, l1);
                *(__nv_bfloat162*)(AL + 4 * i + 2) = __halves2bfloat162(l2, l3);
            }
        }
        __syncthreads();

        // ---- K loop: 16 kc x 3 gates; slot g3 reloaded with (kc+1, g3) ----
        #pragma unroll
        for (int kc = 0; kc < 16; ++kc) {
            uint32_t ah[2][4], al4[2][4];
            #pragma unroll
            for (int mi = 0; mi < 2; ++mi) {
                uint32_t addr = ahi_base +
                    ((arow + 16 * mi) * SPA + kc * 16 + acp) * 2;
                LDSM_X4(ah[mi][0], ah[mi][1], ah[mi][2], ah[mi][3], addr);
                addr = alo_base + ((arow + 16 * mi) * SPA + kc * 16 + acp) * 2;
                LDSM_X4(al4[mi][0], al4[mi][1], al4[mi][2], al4[mi][3], addr);
            }
            #pragma unroll
            for (int g3 = 0; g3 < 3; ++g3) {
                #pragma unroll
                for (int mi = 0; mi < 2; ++mi)
                    #pragma unroll
                    for (int t2 = 0; t2 < 2; ++t2) {
                        MMA16816(c[mi][4 * g3 + 2 * t2],     ah[mi], bh[g3][t2].x, bh[g3][t2].y);
                        MMA16816(c[mi][4 * g3 + 2 * t2 + 1], ah[mi], bh[g3][t2].z, bh[g3][t2].w);
                    }
                #pragma unroll
                for (int mi = 0; mi < 2; ++mi)
                    #pragma unroll
                    for (int t2 = 0; t2 < 2; ++t2) {
                        MMA16816(c[mi][4 * g3 + 2 * t2],     al4[mi], bh[g3][t2].x, bh[g3][t2].y);
                        MMA16816(c[mi][4 * g3 + 2 * t2 + 1], al4[mi], bh[g3][t2].z, bh[g3][t2].w);
                    }
                #pragma unroll
                for (int mi = 0; mi < 2; ++mi)
                    #pragma unroll
                    for (int t2 = 0; t2 < 2; ++t2) {
                        MMA16816(c[mi][4 * g3 + 2 * t2],     ah[mi], bl[g3][t2].x, bl[g3][t2].y);
                        MMA16816(c[mi][4 * g3 + 2 * t2 + 1], ah[mi], bl[g3][t2].z, bl[g3][t2].w);
                    }
                {
                    const int base = ((((kc + 1) & 15) * 48) + g3 * 16) * 32;
                    #pragma unroll
                    for (int t2 = 0; t2 < 2; ++t2) {
                        bh[g3][t2] = g_Wfh[base + wf_lane + t2 * 32];
                        bl[g3][t2] = g_Wfl[base + wf_lane + t2 * 32];
                    }
                }
            }
        }

        // ---- epilogue: gates + gated h update (thread-local positions) ----
        #pragma unroll
        for (int mi = 0; mi < 2; ++mi) {
            #pragma unroll
            for (int ni = 0; ni < 4; ++ni) {
                int j = 32 * w + 8 * ni + qcol;
                #pragma unroll
                for (int rh = 0; rh < 2; ++rh) {
                    int b = 16 * mi + qrow + 8 * rh;
                    float g = gS[b];
                    float2 hp = *(const float2*)&hS[b * SPH + j];
                    float res[2];
                    #pragma unroll
                    for (int q2 = 0; q2 < 2; ++q2) {
                        int q = 2 * rh + q2;
                        float r = fast_sigmoid(c[mi][ni][q]);
                        float z = fast_sigmoid(c[mi][ni + 4][q]);
                        float hn = c[mi][ni + 8][q];         // h·Whn + b_hh_n
                        float n = fast_tanh(gin[mi][ni][q] + r * hn);
                        float hprev = q2 ? hp.y : hp.x;
                        float hnew = (1.f - z) * n + z * hprev;
                        res[q2] = g * hnew + (1.f - g) * hprev;
                    }
                    *(float2*)&hS[b * SPH + j] = make_float2(res[0], res[1]);
                }
            }
        }
        __syncthreads();
    }

    // ---- final output ----
    #pragma unroll 1
    for (int r = 0; r < TB; ++r)
        out[(size_t)(bbase + r) * HID + tid] = hS[r * SPH + tid];
}

// ============================ Launch =======================================
extern "C" void kernel_launch(void* const* d_in, const int* in_sizes, int n_in,
                              void* d_out, int out_size) {
    const float* C   = (const float*)d_in[0];
    const float* G   = (const float*)d_in[1];
    const float* Wih = (const float*)d_in[2];
    const float* Whh = (const float*)d_in[3];
    const float* bih = (const float*)d_in[4];
    const float* bhh = (const float*)d_in[5];
    float* out = (float*)d_out;

    cudaFuncSetAttribute(phase1_mma_kernel,
                         cudaFuncAttributeMaxDynamicSharedMemorySize, P1_SMEM);
    cudaFuncSetAttribute(gru_scan_tc,
                         cudaFuncAttributeMaxDynamicSharedMemorySize, SCN_SMEM);

    split_c_kernel<<<NROW, 256>>>(C);
    wfrag_kernel<<<96, 256>>>(Whh, 0);
    wfrag_kernel<<<96, 256>>>(Wih, 1);
    biasc_kernel<<<3, 256>>>(bih, bhh);

    phase1_mma_kernel<<<dim3(NG / BN, NROW / BM), 256, P1_SMEM>>>();

    gru_scan_tc<<<NCTA, SNT, SCN_SMEM>>>(G, bhh, out);
}

// round 17
// speedup vs baseline: 2.4231x; 1.0063x over previous
#include <cuda_runtime.h>
#include <cuda_pipeline.h>
#include <cuda_bf16.h>
#include <cstdint>

// ============================ Problem constants ============================
#define B_TOT 4096
#define SEQ   50
#define HID   256
#define NROW  (B_TOT * SEQ)      // 204800 rows of C (b*50+s)
#define NG    768                // 3 gates * 256
#define NMT   (NROW / 16)        // 12800 m16 tiles

// ============================ Device scratch ===============================
// C splits in mma-A fragment order: index ((mt*32 + kt)*32 + lane),
// kt 0..15 = hi band, 16..31 = lo band. One uint4 per lane per 16x16 tile.
__device__ uint4         g_Cf[(size_t)NMT * 32 * 32];  // 210 MB
__device__ float         g_gi[(size_t)NROW * NG];      // gi + combined bias
__device__ float         g_biasc[NG];                  // b_ih (+ b_hh for r,z)
// W in mma-B fragment order: tile (kc,nt) = 16x16, one uint4 per lane.
// index = (kc*48 + nt)*32 + lane,  kc in [0,16), nt in [0,48)
__device__ uint4         g_Wfh[16 * 48 * 32];          // W_hh hi split
__device__ uint4         g_Wfl[16 * 48 * 32];          // W_hh lo split
__device__ uint4         g_Wihfh[16 * 48 * 32];        // W_ih hi split
__device__ uint4         g_Wihfl[16 * 48 * 32];        // W_ih lo split

// ============================ helpers ======================================
__device__ __forceinline__ uint32_t smem_u32(const void* p) {
    uint32_t a;
    asm("{ .reg .u64 t; cvta.to.shared.u64 t, %1; cvt.u32.u64 %0, t; }"
        : "=r"(a) : "l"(p));
    return a;
}

#define LDSM_X4(r0, r1, r2, r3, addr) \
    asm volatile("ldmatrix.sync.aligned.m8n8.x4.shared.b16 {%0,%1,%2,%3}, [%4];" \
        : "=r"(r0), "=r"(r1), "=r"(r2), "=r"(r3) : "r"(addr))

#define MMA16816(c, a, b0, b1) \
    asm volatile("mma.sync.aligned.m16n8k16.row.col.f32.bf16.bf16.f32 " \
        "{%0,%1,%2,%3}, {%4,%5,%6,%7}, {%8,%9}, {%0,%1,%2,%3};" \
        : "+f"((c)[0]), "+f"((c)[1]), "+f"((c)[2]), "+f"((c)[3]) \
        : "r"((a)[0]), "r"((a)[1]), "r"((a)[2]), "r"((a)[3]), "r"(b0), "r"(b1))

// MMA with A given as uint4 fragment
#define MMA16816U(c, av, b0, b1) \
    asm volatile("mma.sync.aligned.m16n8k16.row.col.f32.bf16.bf16.f32 " \
        "{%0,%1,%2,%3}, {%4,%5,%6,%7}, {%8,%9}, {%0,%1,%2,%3};" \
        : "+f"((c)[0]), "+f"((c)[1]), "+f"((c)[2]), "+f"((c)[3]) \
        : "r"((av).x), "r"((av).y), "r"((av).z), "r"((av).w), "r"(b0), "r"(b1))

__device__ __forceinline__ float fast_sigmoid(float x) {
    return __fdividef(1.f, 1.f + __expf(-x));
}
__device__ __forceinline__ float fast_tanh(float x) {
    x = fminf(fmaxf(x, -30.f), 30.f);
    float e = __expf(-2.f * x);
    return __fdividef(1.f - e, 1.f + e);
}

__device__ __forceinline__ uint32_t pk_hi(float a, float b) {
    __nv_bfloat162 h = __floats2bfloat162_rn(a, b);
    return *(uint32_t*)&h;
}
__device__ __forceinline__ uint32_t pk_lo(float a, float b) {
    float ar = a - __bfloat162float(__float2bfloat16(a));
    float br = b - __bfloat162float(__float2bfloat16(b));
    __nv_bfloat162 h = __floats2bfloat162_rn(ar, br);
    return *(uint32_t*)&h;
}

// ============================ Prep kernels =================================
// C -> A-fragment order, both bands, reading C once.
// threads = NMT*16*32 = 6,553,600  -> 25600 blocks of 256
__global__ void cfrag_kernel(const float* __restrict__ C) {
    size_t t = (size_t)blockIdx.x * 256 + threadIdx.x;
    int lane = (int)(t & 31);
    size_t tile = t >> 5;            // mt*16 + kt
    int kt = (int)(tile & 15);
    size_t mt = tile >> 4;
    int q  = lane >> 2;
    int k0 = (lane & 3) * 2;
    size_t r0 = mt * 16 + q;
    int col = kt * 16 + k0;
    const float* c0 = C + r0 * HID + col;
    const float* c8 = C + (r0 + 8) * HID + col;
    float a0 = c0[0], a1 = c0[1], a2 = c0[8], a3 = c0[9];
    float b0 = c8[0], b1 = c8[1], b2 = c8[8], b3 = c8[9];
    uint4 vh, vl;
    vh.x = pk_hi(a0, a1); vh.y = pk_hi(b0, b1);
    vh.z = pk_hi(a2, a3); vh.w = pk_hi(b2, b3);
    vl.x = pk_lo(a0, a1); vl.y = pk_lo(b0, b1);
    vl.z = pk_lo(a2, a3); vl.w = pk_lo(b2, b3);
    g_Cf[(mt * 32 + kt) * 32 + lane]      = vh;
    g_Cf[(mt * 32 + 16 + kt) * 32 + lane] = vl;
}

// W[768][256] -> mma-B fragment order, hi/lo splits. which: 0 = W_hh, 1 = W_ih
__global__ void wfrag_kernel(const float* __restrict__ W, int which) {
    int t = blockIdx.x * 256 + threadIdx.x;    // 96 blocks * 256 = 24576
    int lane = t & 31;
    int tile = t >> 5;                          // kc*48 + nt
    int nt = tile % 48, kc = tile / 48;
    int r  = nt * 16 + (lane >> 2);
    int k0 = kc * 16 + (lane & 3) * 2;
    const float* w0 = W + (size_t)r * HID;
    const float* w8 = W + (size_t)(r + 8) * HID;
    float a0 = w0[k0], a1 = w0[k0 + 1], a8 = w0[k0 + 8], a9 = w0[k0 + 9];
    float b0 = w8[k0], b1 = w8[k0 + 1], b8 = w8[k0 + 8], b9 = w8[k0 + 9];
    uint4 vh, vl;
    vh.x = pk_hi(a0, a1); vh.y = pk_hi(a8, a9);
    vh.z = pk_hi(b0, b1); vh.w = pk_hi(b8, b9);
    vl.x = pk_lo(a0, a1); vl.y = pk_lo(a8, a9);
    vl.z = pk_lo(b0, b1); vl.w = pk_lo(b8, b9);
    if (which) { g_Wihfh[t] = vh; g_Wihfl[t] = vl; }
    else       { g_Wfh[t]   = vh; g_Wfl[t]   = vl; }
}

__global__ void biasc_kernel(const float* __restrict__ bih,
                             const float* __restrict__ bhh) {
    int n = blockIdx.x * 256 + threadIdx.x;                // 3 blocks
    g_biasc[n] = bih[n] + (n < 512 ? bhh[n] : 0.f);
}

// ============================ Phase 1: gi GEMM (mma.sync) ==================
// Fully smem-free: A and B fragments streamed via LDG.128 rings (distance 2).
// hi band (kt 0..15): c += a*Whi; c += a*Wlo.   lo band (kt 16..31): c += a*Whi.
#define BN 128

__global__ void __launch_bounds__(256)
phase1_mma_kernel() {
    const int tid  = threadIdx.x;
    const int lane = tid & 31;
    const int wid  = tid >> 5;
    const int wm   = wid & 1;
    const int wn   = wid >> 1;
    const int n0   = blockIdx.x * BN;
    const size_t mtb = (size_t)blockIdx.y * 8 + wm * 4;   // first m16 tile
    const int ntb  = (n0 >> 4) + wn * 2;                  // first n16 tile

    float c[4][4][4];
    #pragma unroll
    for (int i = 0; i < 4; ++i)
        #pragma unroll
        for (int j = 0; j < 4; ++j)
            #pragma unroll
            for (int q = 0; q < 4; ++q) c[i][j][q] = 0.f;

    // A ring (distance 2): preload kt = 0, 1
    uint4 af[2][4];
    #pragma unroll
    for (int pi = 0; pi < 2; ++pi)
        #pragma unroll
        for (int mi = 0; mi < 4; ++mi)
            af[pi][mi] = g_Cf[((mtb + mi) * 32 + pi) * 32 + lane];

    // B ring (distance 2): preload kt = 0, 1 (hi band)
    uint4 bfh[2][2], bfl[2][2];
    #pragma unroll
    for (int pi = 0; pi < 2; ++pi)
        #pragma unroll
        for (int t2 = 0; t2 < 2; ++t2) {
            bfh[pi][t2] = g_Wihfh[((size_t)pi * 48 + ntb + t2) * 32 + lane];
            bfl[pi][t2] = g_Wihfl[((size_t)pi * 48 + ntb + t2) * 32 + lane];
        }

    // ---- hi band: kt 0..15, 2 B terms per kt ----
    #pragma unroll
    for (int kt = 0; kt < 16; ++kt) {
        const int p = kt & 1;
        #pragma unroll
        for (int t2 = 0; t2 < 2; ++t2)
            #pragma unroll
            for (int mi = 0; mi < 4; ++mi) {
                MMA16816U(c[mi][t2 * 2],     af[p][mi], bfh[p][t2].x, bfh[p][t2].y);
                MMA16816U(c[mi][t2 * 2 + 1], af[p][mi], bfh[p][t2].z, bfh[p][t2].w);
            }
        #pragma unroll
        for (int t2 = 0; t2 < 2; ++t2)
            #pragma unroll
            for (int mi = 0; mi < 4; ++mi) {
                MMA16816U(c[mi][t2 * 2],     af[p][mi], bfl[p][t2].x, bfl[p][t2].y);
                MMA16816U(c[mi][t2 * 2 + 1], af[p][mi], bfl[p][t2].z, bfl[p][t2].w);
            }
        // refill slot p with kt+2
        {
            const int ktn = kt + 2;
            #pragma unroll
            for (int mi = 0; mi < 4; ++mi)
                af[p][mi] = g_Cf[((mtb + mi) * 32 + ktn) * 32 + lane];
            if (ktn < 16) {
                #pragma unroll
                for (int t2 = 0; t2 < 2; ++t2) {
                    bfh[p][t2] = g_Wihfh[((size_t)ktn * 48 + ntb + t2) * 32 + lane];
                    bfl[p][t2] = g_Wihfl[((size_t)ktn * 48 + ntb + t2) * 32 + lane];
                }
            } else {    // lo band needs W_hi frags of (ktn-16)
                #pragma unroll
                for (int t2 = 0; t2 < 2; ++t2)
                    bfh[p][t2] = g_Wihfh[((size_t)(ktn - 16) * 48 + ntb + t2) * 32 + lane];
            }
        }
    }

    // ---- lo band: kt 16..31, 1 B term per kt ----
    #pragma unroll
    for (int kt = 16; kt < 32; ++kt) {
        const int p = kt & 1;
        #pragma unroll
        for (int t2 = 0; t2 < 2; ++t2)
            #pragma unroll
            for (int mi = 0; mi < 4; ++mi) {
                MMA16816U(c[mi][t2 * 2],     af[p][mi], bfh[p][t2].x, bfh[p][t2].y);
                MMA16816U(c[mi][t2 * 2 + 1], af[p][mi], bfh[p][t2].z, bfh[p][t2].w);
            }
        {
            const int ktn = kt + 2;
            if (ktn < 32) {
                #pragma unroll
                for (int mi = 0; mi < 4; ++mi)
                    af[p][mi] = g_Cf[((mtb + mi) * 32 + ktn) * 32 + lane];
                #pragma unroll
                for (int t2 = 0; t2 < 2; ++t2)
                    bfh[p][t2] = g_Wihfh[((size_t)(ktn - 16) * 48 + ntb + t2) * 32 + lane];
            }
        }
    }

    // epilogue: add combined bias, store
    const size_t m0 = (size_t)blockIdx.y * 128;
    const int r_base = wm * 64 + (lane >> 2);
    const int c_base = n0 + wn * 32 + (lane & 3) * 2;
    #pragma unroll
    for (int ni = 0; ni < 4; ++ni) {
        int col = c_base + ni * 8;
        float2 bv = *(const float2*)&g_biasc[col];
        #pragma unroll
        for (int mi = 0; mi < 4; ++mi) {
            size_t row = m0 + r_base + mi * 16;
            *(float2*)&g_gi[row * NG + col] =
                make_float2(c[mi][ni][0] + bv.x, c[mi][ni][1] + bv.y);
            *(float2*)&g_gi[(row + 8) * NG + col] =
                make_float2(c[mi][ni][2] + bv.x, c[mi][ni][3] + bv.y);
        }
    }
}

// ============================ Phase 2: tensor-core scan ====================
#define TB    32
#define NCTA  (B_TOT / TB)        // 128
#define SNT   256
#define SPA   264                 // A pitch (elems), 528B = 33*16B
#define SPH   260                 // h pitch (floats)

#define OFF_AHI 0                                   // 32*264*2 = 16896
#define OFF_ALO (OFF_AHI + 32 * SPA * 2)            // 16896
#define OFF_H   (OFF_ALO + 32 * SPA * 2)            // 33792, 32*260*4 = 33280
#define OFF_BHN (OFF_H + 32 * SPH * 4)              // 67072, 1024
#define OFF_G   (OFF_BHN + 256 * 4)                 // 68096, 128
#define SCN_SMEM (OFF_G + 32 * 4)                   // 68224

__global__ void __launch_bounds__(SNT, 1)
gru_scan_tc(const float* __restrict__ G, const float* __restrict__ b_hh,
            float* __restrict__ out)
{
    extern __shared__ char smp[];
    const int tid  = threadIdx.x;
    const int lane = tid & 31;
    const int w    = tid >> 5;                 // 8 warps, each owns 3x32 n-cols
    const int bbase = blockIdx.x * TB;
    const int qrow = lane >> 2;
    const int qcol = (lane & 3) * 2;

    float* hS   = (float*)(smp + OFF_H);
    float* bhnS = (float*)(smp + OFF_BHN);
    float* gS   = (float*)(smp + OFF_G);

    for (int i = tid; i < 32 * SPH; i += SNT) hS[i] = 0.f;
    bhnS[tid] = b_hh[512 + tid];
    __syncthreads();

    float2 bnv[4];
    #pragma unroll
    for (int ni = 0; ni < 4; ++ni)
        bnv[ni] = *(const float2*)&bhnS[32 * w + 8 * ni + qcol];

    const uint32_t ahi_base = smem_u32(smp + OFF_AHI);
    const uint32_t alo_base = smem_u32(smp + OFF_ALO);
    const int arow = lane & 15;
    const int acp  = (lane >> 4) * 8;
    const int wf_lane = 2 * w * 32 + lane;

    // ---- B ring preload: slot g3 holds stage (kc=0, g3) ----
    uint4 bh[3][2], bl[3][2];
    #pragma unroll
    for (int pi = 0; pi < 3; ++pi) {
        const int base = (pi * 16) * 32;
        #pragma unroll
        for (int t2 = 0; t2 < 2; ++t2) {
            bh[pi][t2] = g_Wfh[base + wf_lane + t2 * 32];
            bl[pi][t2] = g_Wfl[base + wf_lane + t2 * 32];
        }
    }

    #pragma unroll 1
    for (int s = 0; s < SEQ; ++s) {
        // ---- accumulator init: aligned float2 gi loads (issued first) ----
        float c[2][12][4];
        float gin[2][4][4];
        #pragma unroll
        for (int mi = 0; mi < 2; ++mi) {
            size_t r0 = ((size_t)(bbase + 16 * mi + qrow) * SEQ + s) * NG;
            size_t r1 = r0 + (size_t)8 * SEQ * NG;
            #pragma unroll
            for (int ni = 0; ni < 4; ++ni) {
                int col = 32 * w + 8 * ni + qcol;
                float2 a0 = *(const float2*)&g_gi[r0 + col];
                float2 a1 = *(const float2*)&g_gi[r1 + col];
                float2 z0 = *(const float2*)&g_gi[r0 + 256 + col];
                float2 z1 = *(const float2*)&g_gi[r1 + 256 + col];
                float2 n0 = *(const float2*)&g_gi[r0 + 512 + col];
                float2 n1 = *(const float2*)&g_gi[r1 + 512 + col];
                c[mi][ni][0] = a0.x;  c[mi][ni][1] = a0.y;
                c[mi][ni][2] = a1.x;  c[mi][ni][3] = a1.y;
                c[mi][ni + 4][0] = z0.x;  c[mi][ni + 4][1] = z0.y;
                c[mi][ni + 4][2] = z1.x;  c[mi][ni + 4][3] = z1.y;
                gin[mi][ni][0] = n0.x;  gin[mi][ni][1] = n0.y;
                gin[mi][ni][2] = n1.x;  gin[mi][ni][3] = n1.y;
                c[mi][ni + 8][0] = bnv[ni].x;  c[mi][ni + 8][1] = bnv[ni].y;
                c[mi][ni + 8][2] = bnv[ni].x;  c[mi][ni + 8][3] = bnv[ni].y;
            }
        }
        if (tid < TB) gS[tid] = G[(size_t)(bbase + tid) * SEQ + s];

        // ---- convert h fp32 -> A_hi/A_lo bf16 (hides gi load latency) ----
        {
            int b = tid >> 3, kb = (tid & 7) * 32;
            const float* hr = hS + b * SPH + kb;
            __nv_bfloat16* AH = (__nv_bfloat16*)(smp + OFF_AHI) + b * SPA + kb;
            __nv_bfloat16* AL = (__nv_bfloat16*)(smp + OFF_ALO) + b * SPA + kb;
            #pragma unroll
            for (int i = 0; i < 8; ++i) {
                float4 v = *(const float4*)(hr + 4 * i);
                __nv_bfloat16 h0 = __float2bfloat16(v.x);
                __nv_bfloat16 h1 = __float2bfloat16(v.y);
                __nv_bfloat16 h2 = __float2bfloat16(v.z);
                __nv_bfloat16 h3 = __float2bfloat16(v.w);
                __nv_bfloat16 l0 = __float2bfloat16(v.x - __bfloat162float(h0));
                __nv_bfloat16 l1 = __float2bfloat16(v.y - __bfloat162float(h1));
                __nv_bfloat16 l2 = __float2bfloat16(v.z - __bfloat162float(h2));
                __nv_bfloat16 l3 = __float2bfloat16(v.w - __bfloat162float(h3));
                *(__nv_bfloat162*)(AH + 4 * i)     = __halves2bfloat162(h0, h1);
                *(__nv_bfloat162*)(AH + 4 * i + 2) = __halves2bfloat162(h2, h3);
                *(__nv_bfloat162*)(AL + 4 * i)     = __halves2bfloat162(l0, l1);
                *(__nv_bfloat162*)(AL + 4 * i + 2) = __halves2bfloat162(l2, l3);
            }
        }
        __syncthreads();

        // ---- K loop: 16 kc x 3 gates; slot g3 reloaded with (kc+1, g3) ----
        #pragma unroll
        for (int kc = 0; kc < 16; ++kc) {
            uint32_t ah[2][4], al4[2][4];
            #pragma unroll
            for (int mi = 0; mi < 2; ++mi) {
                uint32_t addr = ahi_base +
                    ((arow + 16 * mi) * SPA + kc * 16 + acp) * 2;
                LDSM_X4(ah[mi][0], ah[mi][1], ah[mi][2], ah[mi][3], addr);
                addr = alo_base + ((arow + 16 * mi) * SPA + kc * 16 + acp) * 2;
                LDSM_X4(al4[mi][0], al4[mi][1], al4[mi][2], al4[mi][3], addr);
            }
            #pragma unroll
            for (int g3 = 0; g3 < 3; ++g3) {
                #pragma unroll
                for (int mi = 0; mi < 2; ++mi)
                    #pragma unroll
                    for (int t2 = 0; t2 < 2; ++t2) {
                        MMA16816(c[mi][4 * g3 + 2 * t2],     ah[mi], bh[g3][t2].x, bh[g3][t2].y);
                        MMA16816(c[mi][4 * g3 + 2 * t2 + 1], ah[mi], bh[g3][t2].z, bh[g3][t2].w);
                    }
                #pragma unroll
                for (int mi = 0; mi < 2; ++mi)
                    #pragma unroll
                    for (int t2 = 0; t2 < 2; ++t2) {
                        MMA16816(c[mi][4 * g3 + 2 * t2],     al4[mi], bh[g3][t2].x, bh[g3][t2].y);
                        MMA16816(c[mi][4 * g3 + 2 * t2 + 1], al4[mi], bh[g3][t2].z, bh[g3][t2].w);
                    }
                #pragma unroll
                for (int mi = 0; mi < 2; ++mi)
                    #pragma unroll
                    for (int t2 = 0; t2 < 2; ++t2) {
                        MMA16816(c[mi][4 * g3 + 2 * t2],     ah[mi], bl[g3][t2].x, bl[g3][t2].y);
                        MMA16816(c[mi][4 * g3 + 2 * t2 + 1], ah[mi], bl[g3][t2].z, bl[g3][t2].w);
                    }
                {
                    const int base = ((((kc + 1) & 15) * 48) + g3 * 16) * 32;
                    #pragma unroll
                    for (int t2 = 0; t2 < 2; ++t2) {
                        bh[g3][t2] = g_Wfh[base + wf_lane + t2 * 32];
                        bl[g3][t2] = g_Wfl[base + wf_lane + t2 * 32];
                    }
                }
            }
        }

        // ---- epilogue: gates + gated h update (thread-local positions) ----
        #pragma unroll
        for (int mi = 0; mi < 2; ++mi) {
            #pragma unroll
            for (int ni = 0; ni < 4; ++ni) {
                int j = 32 * w + 8 * ni + qcol;
                #pragma unroll
                for (int rh = 0; rh < 2; ++rh) {
                    int b = 16 * mi + qrow + 8 * rh;
                    float g = gS[b];
                    float2 hp = *(const float2*)&hS[b * SPH + j];
                    float res[2];
                    #pragma unroll
                    for (int q2 = 0; q2 < 2; ++q2) {
                        int q = 2 * rh + q2;
                        float r = fast_sigmoid(c[mi][ni][q]);
                        float z = fast_sigmoid(c[mi][ni + 4][q]);
                        float hn = c[mi][ni + 8][q];         // h·Whn + b_hh_n
                        float n = fast_tanh(gin[mi][ni][q] + r * hn);
                        float hprev = q2 ? hp.y : hp.x;
                        float hnew = (1.f - z) * n + z * hprev;
                        res[q2] = g * hnew + (1.f - g) * hprev;
                    }
                    *(float2*)&hS[b * SPH + j] = make_float2(res[0], res[1]);
                }
            }
        }
        __syncthreads();
    }

    // ---- final output ----
    #pragma unroll 1
    for (int r = 0; r < TB; ++r)
        out[(size_t)(bbase + r) * HID + tid] = hS[r * SPH + tid];
}

// ============================ Launch =======================================
extern "C" void kernel_launch(void* const* d_in, const int* in_sizes, int n_in,
                              void* d_out, int out_size) {
    const float* C   = (const float*)d_in[0];
    const float* G   = (const float*)d_in[1];
    const float* Wih = (const float*)d_in[2];
    const float* Whh = (const float*)d_in[3];
    const float* bih = (const float*)d_in[4];
    const float* bhh = (const float*)d_in[5];
    float* out = (float*)d_out;

    cudaFuncSetAttribute(gru_scan_tc,
                         cudaFuncAttributeMaxDynamicSharedMemorySize, SCN_SMEM);

    cfrag_kernel<<<25600, 256>>>(C);
    wfrag_kernel<<<96, 256>>>(Whh, 0);
    wfrag_kernel<<<96, 256>>>(Wih, 1);
    biasc_kernel<<<3, 256>>>(bih, bhh);

    phase1_mma_kernel<<<dim3(NG / BN, NROW / 128), 256>>>();

    gru_scan_tc<<<NCTA, SNT, SCN_SMEM>>>(G, bhh, out);
}